// round 1
// baseline (speedup 1.0000x reference)
#include <cuda_runtime.h>
#include <math.h>

#define SEQ 4096
#define DIM 768
#define NH  12
#define HDD 64
#define FFD 3072

// ---------------- scratch (device globals; no allocation allowed) ----------------
__device__ float g_x[SEQ * DIM];        // ln1 output
__device__ float g_q[SEQ * DIM];
__device__ float g_k[SEQ * DIM];
__device__ float g_v[SEQ * DIM];
__device__ float g_attn[SEQ * DIM];     // attention output (pre-WO)
__device__ float g_hidden[SEQ * DIM];   // residual after attention
__device__ float g_y[SEQ * DIM];        // ln2 output
__device__ float g_ff[SEQ * FFD];       // gelu(up) output

// ---------------- block reduction helper ----------------
__device__ __forceinline__ float block_sum_256(float v, float* red) {
    int lane = threadIdx.x & 31;
    int wid  = threadIdx.x >> 5;
    #pragma unroll
    for (int o = 16; o; o >>= 1) v += __shfl_xor_sync(0xffffffffu, v, o);
    if (lane == 0) red[wid] = v;
    __syncthreads();
    float r;
    if (wid == 0) {
        r = (lane < 8) ? red[lane] : 0.f;
        #pragma unroll
        for (int o = 4; o; o >>= 1) r += __shfl_xor_sync(0xffffffffu, r, o);
        if (lane == 0) red[0] = r;
    }
    __syncthreads();
    r = red[0];
    __syncthreads();   // safe reuse of red[] by caller
    return r;
}

// ---------------- LayerNorm: one block per row, 256 threads, D=768 ----------------
__global__ void __launch_bounds__(256) ln_kernel(const float* __restrict__ in,
                                                 const float* __restrict__ w,
                                                 const float* __restrict__ b,
                                                 float* __restrict__ out) {
    __shared__ float red[32];
    int row = blockIdx.x;
    const float* x = in + (size_t)row * DIM;
    int t = threadIdx.x;
    float v0 = x[t], v1 = x[t + 256], v2 = x[t + 512];
    float mu = block_sum_256(v0 + v1 + v2, red) * (1.f / DIM);
    float d0 = v0 - mu, d1 = v1 - mu, d2 = v2 - mu;
    float var = block_sum_256(d0 * d0 + d1 * d1 + d2 * d2, red) * (1.f / DIM);
    float rstd = rsqrtf(var + 1e-5f);
    float* o = out + (size_t)row * DIM;
    o[t]       = d0 * rstd * w[t]       + b[t];
    o[t + 256] = d1 * rstd * w[t + 256] + b[t + 256];
    o[t + 512] = d2 * rstd * w[t + 512] + b[t + 512];
}

// ---------------- SGEMM: C[M,N] = A[M,K] @ B[K,N] + bias, epilogue variants --------
// EPI: 0 = bias only, 1 = bias + exact GELU, 2 = bias + residual add
template <int EPI>
__global__ void __launch_bounds__(256) gemm_kernel(const float* __restrict__ A,
                                                   const float* __restrict__ B,
                                                   const float* __restrict__ bias,
                                                   const float* __restrict__ res,
                                                   float* __restrict__ C,
                                                   int M, int N, int K) {
    __shared__ float As[16][64];   // [k][m] (transposed)
    __shared__ float Bs[16][64];   // [k][n]
    int tid = threadIdx.x;
    int tx = tid & 15, ty = tid >> 4;
    int bm = blockIdx.y * 64, bn = blockIdx.x * 64;

    float acc[4][4] = {};

    int arow = tid >> 2;          // 0..63
    int acol = (tid & 3) * 4;     // 0,4,8,12
    int brow = tid >> 4;          // 0..15
    int bcol = (tid & 15) * 4;    // 0..60

    const float* Aptr = A + (size_t)(bm + arow) * K + acol;
    const float* Bptr = B + (size_t)brow * N + bn + bcol;

    for (int k0 = 0; k0 < K; k0 += 16) {
        float4 av = *(const float4*)Aptr;
        float4 bv = *(const float4*)Bptr;
        As[acol + 0][arow] = av.x;
        As[acol + 1][arow] = av.y;
        As[acol + 2][arow] = av.z;
        As[acol + 3][arow] = av.w;
        *(float4*)&Bs[brow][bcol] = bv;
        __syncthreads();
        #pragma unroll
        for (int k = 0; k < 16; k++) {
            float4 a = *(const float4*)&As[k][ty * 4];
            float4 b = *(const float4*)&Bs[k][tx * 4];
            float ar[4] = {a.x, a.y, a.z, a.w};
            float br[4] = {b.x, b.y, b.z, b.w};
            #pragma unroll
            for (int i = 0; i < 4; i++)
                #pragma unroll
                for (int j = 0; j < 4; j++)
                    acc[i][j] = fmaf(ar[i], br[j], acc[i][j]);
        }
        __syncthreads();
        Aptr += 16;
        Bptr += (size_t)16 * N;
    }

    #pragma unroll
    for (int i = 0; i < 4; i++) {
        int row = bm + ty * 4 + i;
        float4 cv;
        float cc[4];
        #pragma unroll
        for (int j = 0; j < 4; j++) {
            int col = bn + tx * 4 + j;
            float c = acc[i][j] + bias[col];
            if (EPI == 1) c = 0.5f * c * (1.f + erff(c * 0.70710678118654752f));
            if (EPI == 2) c += res[(size_t)row * N + col];
            cc[j] = c;
        }
        cv.x = cc[0]; cv.y = cc[1]; cv.z = cc[2]; cv.w = cc[3];
        *(float4*)&C[(size_t)row * N + bn + tx * 4] = cv;
    }
}

// ---------------- Causal flash attention: 64x64 tiles, online softmax -------------
// Q/K/V layout: [S, D] row-major, head h occupies columns [h*64, h*64+64)
__global__ void __launch_bounds__(256) attn_kernel(const float* __restrict__ q,
                                                   const float* __restrict__ k,
                                                   const float* __restrict__ v,
                                                   const int* __restrict__ amask,
                                                   float* __restrict__ o) {
    __shared__ float Qs[64 * 64];   // [d][r] (transposed), pre-scaled by 1/8
    __shared__ float KP[64 * 64];   // Ks [d][c], then reused as Ps [r][kk]
    __shared__ float Vs[64 * 64];   // [c][d]

    int head = blockIdx.y;
    int qb = blockIdx.x;
    int tid = threadIdx.x, tx = tid & 15, ty = tid >> 4;
    int hc = head * HDD;

    // load Q tile (scaled by 1/sqrt(64))
    #pragma unroll
    for (int it = 0; it < 4; it++) {
        int r = (tid >> 4) + it * 16;
        int d4 = (tid & 15) * 4;
        float4 qv = *(const float4*)(q + (size_t)(qb * 64 + r) * DIM + hc + d4);
        Qs[(d4 + 0) * 64 + r] = qv.x * 0.125f;
        Qs[(d4 + 1) * 64 + r] = qv.y * 0.125f;
        Qs[(d4 + 2) * 64 + r] = qv.z * 0.125f;
        Qs[(d4 + 3) * 64 + r] = qv.w * 0.125f;
    }

    float m_[4], l_[4], acc[4][4];
    #pragma unroll
    for (int i = 0; i < 4; i++) {
        m_[i] = -1e30f;
        l_[i] = 0.f;
        #pragma unroll
        for (int j = 0; j < 4; j++) acc[i][j] = 0.f;
    }

    for (int kb = 0; kb <= qb; kb++) {
        __syncthreads();
        // load K (transposed) and V (direct)
        #pragma unroll
        for (int it = 0; it < 4; it++) {
            int c = (tid >> 4) + it * 16;
            int d4 = (tid & 15) * 4;
            const float* kp = k + (size_t)(kb * 64 + c) * DIM + hc + d4;
            float4 kv = *(const float4*)kp;
            KP[(d4 + 0) * 64 + c] = kv.x;
            KP[(d4 + 1) * 64 + c] = kv.y;
            KP[(d4 + 2) * 64 + c] = kv.z;
            KP[(d4 + 3) * 64 + c] = kv.w;
            float4 vv = *(const float4*)(v + (size_t)(kb * 64 + c) * DIM + hc + d4);
            *(float4*)&Vs[c * 64 + d4] = vv;
        }
        __syncthreads();

        // scores S = (Q/8) K^T
        float s[4][4] = {};
        #pragma unroll
        for (int d = 0; d < 64; d++) {
            float4 a = *(const float4*)&Qs[d * 64 + ty * 4];
            float4 b = *(const float4*)&KP[d * 64 + tx * 4];
            float ar[4] = {a.x, a.y, a.z, a.w};
            float br[4] = {b.x, b.y, b.z, b.w};
            #pragma unroll
            for (int i = 0; i < 4; i++)
                #pragma unroll
                for (int j = 0; j < 4; j++)
                    s[i][j] = fmaf(ar[i], br[j], s[i][j]);
        }

        // causal + pad masking
        bool diag = (kb == qb);
        #pragma unroll
        for (int j = 0; j < 4; j++) {
            int kc = kb * 64 + tx * 4 + j;
            bool pad = (amask[kc] == 0);
            #pragma unroll
            for (int i = 0; i < 4; i++) {
                int qr = qb * 64 + ty * 4 + i;
                if ((diag && kc > qr) || pad) s[i][j] = -1e30f;
            }
        }

        // online softmax (row reductions over 16 tx lanes)
        #pragma unroll
        for (int i = 0; i < 4; i++) {
            float rmax = fmaxf(fmaxf(s[i][0], s[i][1]), fmaxf(s[i][2], s[i][3]));
            #pragma unroll
            for (int off = 1; off < 16; off <<= 1)
                rmax = fmaxf(rmax, __shfl_xor_sync(0xffffffffu, rmax, off));
            float mn = fmaxf(m_[i], rmax);
            float f = __expf(m_[i] - mn);
            float rsum = 0.f;
            #pragma unroll
            for (int j = 0; j < 4; j++) {
                s[i][j] = __expf(s[i][j] - mn);
                rsum += s[i][j];
            }
            #pragma unroll
            for (int off = 1; off < 16; off <<= 1)
                rsum += __shfl_xor_sync(0xffffffffu, rsum, off);
            l_[i] = l_[i] * f + rsum;
            m_[i] = mn;
            #pragma unroll
            for (int j = 0; j < 4; j++) acc[i][j] *= f;
        }

        __syncthreads();   // all done reading KP as K
        // write P into KP as [row][key]
        #pragma unroll
        for (int i = 0; i < 4; i++) {
            float4 pv;
            pv.x = s[i][0]; pv.y = s[i][1]; pv.z = s[i][2]; pv.w = s[i][3];
            *(float4*)&KP[(ty * 4 + i) * 64 + tx * 4] = pv;
        }
        __syncthreads();

        // O += P @ V
        #pragma unroll
        for (int kk = 0; kk < 64; kk++) {
            float4 vv = *(const float4*)&Vs[kk * 64 + tx * 4];
            #pragma unroll
            for (int i = 0; i < 4; i++) {
                float p = KP[(ty * 4 + i) * 64 + kk];
                acc[i][0] = fmaf(p, vv.x, acc[i][0]);
                acc[i][1] = fmaf(p, vv.y, acc[i][1]);
                acc[i][2] = fmaf(p, vv.z, acc[i][2]);
                acc[i][3] = fmaf(p, vv.w, acc[i][3]);
            }
        }
    }

    // normalize + store
    #pragma unroll
    for (int i = 0; i < 4; i++) {
        float inv = 1.f / l_[i];
        float4 ov;
        ov.x = acc[i][0] * inv;
        ov.y = acc[i][1] * inv;
        ov.z = acc[i][2] * inv;
        ov.w = acc[i][3] * inv;
        *(float4*)(o + (size_t)(qb * 64 + ty * 4 + i) * DIM + hc + tx * 4) = ov;
    }
}

// ---------------- launch ----------------
extern "C" void kernel_launch(void* const* d_in, const int* in_sizes, int n_in,
                              void* d_out, int out_size) {
    const float* hs    = (const float*)d_in[0];
    const int*   amask = (const int*)d_in[1];
    const float* ln1w  = (const float*)d_in[2];
    const float* ln1b  = (const float*)d_in[3];
    const float* wq    = (const float*)d_in[4];
    const float* bq    = (const float*)d_in[5];
    const float* wk    = (const float*)d_in[6];
    const float* bk    = (const float*)d_in[7];
    const float* wv    = (const float*)d_in[8];
    const float* bv    = (const float*)d_in[9];
    const float* wo    = (const float*)d_in[10];
    const float* bo    = (const float*)d_in[11];
    const float* ln2w  = (const float*)d_in[12];
    const float* ln2b  = (const float*)d_in[13];
    const float* wup   = (const float*)d_in[14];
    const float* bup   = (const float*)d_in[15];
    const float* wdn   = (const float*)d_in[16];
    const float* bdn   = (const float*)d_in[17];

    float *x, *qb_, *kb_, *vb_, *attn, *hidden, *y, *ff;
    cudaGetSymbolAddress((void**)&x, g_x);
    cudaGetSymbolAddress((void**)&qb_, g_q);
    cudaGetSymbolAddress((void**)&kb_, g_k);
    cudaGetSymbolAddress((void**)&vb_, g_v);
    cudaGetSymbolAddress((void**)&attn, g_attn);
    cudaGetSymbolAddress((void**)&hidden, g_hidden);
    cudaGetSymbolAddress((void**)&y, g_y);
    cudaGetSymbolAddress((void**)&ff, g_ff);

    dim3 gD(DIM / 64, SEQ / 64);
    dim3 gF(FFD / 64, SEQ / 64);

    ln_kernel<<<SEQ, 256>>>(hs, ln1w, ln1b, x);
    gemm_kernel<0><<<gD, 256>>>(x, wq, bq, nullptr, qb_, SEQ, DIM, DIM);
    gemm_kernel<0><<<gD, 256>>>(x, wk, bk, nullptr, kb_, SEQ, DIM, DIM);
    gemm_kernel<0><<<gD, 256>>>(x, wv, bv, nullptr, vb_, SEQ, DIM, DIM);
    attn_kernel<<<dim3(SEQ / 64, NH), 256>>>(qb_, kb_, vb_, amask, attn);
    gemm_kernel<2><<<gD, 256>>>(attn, wo, bo, hs, hidden, SEQ, DIM, DIM);
    ln_kernel<<<SEQ, 256>>>(hidden, ln2w, ln2b, y);
    gemm_kernel<1><<<gF, 256>>>(y, wup, bup, nullptr, ff, SEQ, FFD, DIM);
    gemm_kernel<2><<<gD, 256>>>(ff, wdn, bdn, hidden, (float*)d_out, SEQ, DIM, FFD);
}

// round 3
// speedup vs baseline: 1.2795x; 1.2795x over previous
#include <cuda_runtime.h>
#include <math.h>

#define SEQ 4096
#define DIM 768
#define NH  12
#define HDD 64
#define FFD 3072

// ---------------- scratch (device globals) ----------------
__device__ float g_x[SEQ * DIM];
__device__ float g_q[SEQ * DIM];
__device__ float g_k[SEQ * DIM];
__device__ float g_v[SEQ * DIM];
__device__ float g_attn[SEQ * DIM];
__device__ float g_hidden[SEQ * DIM];
__device__ float g_y[SEQ * DIM];
__device__ float g_ff[SEQ * FFD];

// ---------------- helpers ----------------
__device__ __forceinline__ unsigned f2tf(float f) {
    unsigned r;
    asm("cvt.rna.tf32.f32 %0, %1;" : "=r"(r) : "f"(f));
    return r;
}

__device__ __forceinline__ void mma_tf32(float* c, const unsigned* a, const unsigned* b) {
    asm volatile(
        "mma.sync.aligned.m16n8k8.row.col.f32.tf32.tf32.f32 "
        "{%0,%1,%2,%3}, {%4,%5,%6,%7}, {%8,%9}, {%0,%1,%2,%3};"
        : "+f"(c[0]), "+f"(c[1]), "+f"(c[2]), "+f"(c[3])
        : "r"(a[0]), "r"(a[1]), "r"(a[2]), "r"(a[3]), "r"(b[0]), "r"(b[1]));
}

__device__ __forceinline__ float block_sum_256(float v, float* red) {
    int lane = threadIdx.x & 31;
    int wid  = threadIdx.x >> 5;
    #pragma unroll
    for (int o = 16; o; o >>= 1) v += __shfl_xor_sync(0xffffffffu, v, o);
    if (lane == 0) red[wid] = v;
    __syncthreads();
    float r;
    if (wid == 0) {
        r = (lane < 8) ? red[lane] : 0.f;
        #pragma unroll
        for (int o = 4; o; o >>= 1) r += __shfl_xor_sync(0xffffffffu, r, o);
        if (lane == 0) red[0] = r;
    }
    __syncthreads();
    r = red[0];
    __syncthreads();
    return r;
}

// ---------------- LayerNorm ----------------
__global__ void __launch_bounds__(256) ln_kernel(const float* __restrict__ in,
                                                 const float* __restrict__ w,
                                                 const float* __restrict__ b,
                                                 float* __restrict__ out) {
    __shared__ float red[32];
    int row = blockIdx.x;
    const float* x = in + (size_t)row * DIM;
    int t = threadIdx.x;
    float v0 = x[t], v1 = x[t + 256], v2 = x[t + 512];
    float mu = block_sum_256(v0 + v1 + v2, red) * (1.f / DIM);
    float d0 = v0 - mu, d1 = v1 - mu, d2 = v2 - mu;
    float var = block_sum_256(d0 * d0 + d1 * d1 + d2 * d2, red) * (1.f / DIM);
    float rstd = rsqrtf(var + 1e-5f);
    float* o = out + (size_t)row * DIM;
    o[t]       = d0 * rstd * w[t]       + b[t];
    o[t + 256] = d1 * rstd * w[t + 256] + b[t + 256];
    o[t + 512] = d2 * rstd * w[t + 512] + b[t + 512];
}

// ---------------- TF32 tensor-core GEMM ----------------
// C[M,N] = A[M,K] @ B[K,N] + bias, EPI: 0 none, 1 GELU, 2 residual add
// block 128x128, 8 warps each 64x32, K-tile 16, smem holds mma fragments.
__device__ __forceinline__ void stA_frag(unsigned* s, int base, float4 v) {
    s[base]      = f2tf(v.x);
    s[base + 4]  = f2tf(v.y);
    s[base + 8]  = f2tf(v.z);
    s[base + 12] = f2tf(v.w);
}
__device__ __forceinline__ void stB_frag(unsigned* s, int base, float4 v) {
    s[base]      = f2tf(v.x);
    s[base + 8]  = f2tf(v.y);
    s[base + 16] = f2tf(v.z);
    s[base + 24] = f2tf(v.w);
}

template <int EPI>
__device__ __forceinline__ void gemm_core(const float* __restrict__ A,
                                          const float* __restrict__ B,
                                          const float* __restrict__ bias,
                                          const float* __restrict__ res,
                                          float* __restrict__ C,
                                          int M, int N, int K) {
    __shared__ unsigned sA[2][2048];   // [kstep2][mfrag8] x 512B fragments
    __shared__ unsigned sB[2][2048];   // [kstep2][nfrag16] x 256B fragments
    int tid = threadIdx.x, lane = tid & 31, wid = tid >> 5;
    int wm = wid & 1, wn = wid >> 1;
    int bm = blockIdx.y * 128, bn = blockIdx.x * 128;

    float acc[4][4][4] = {};

    int a_row0 = tid >> 2, a_c4 = tid & 3;
    int a_row1 = a_row0 + 64;
    int b_k0 = tid >> 5, b_c4 = tid & 31;
    int b_k1 = b_k0 + 8;

    const float4* Ap0 = (const float4*)(A + (size_t)(bm + a_row0) * K) + a_c4;
    const float4* Ap1 = (const float4*)(A + (size_t)(bm + a_row1) * K) + a_c4;
    const float4* Bp0 = (const float4*)(B + (size_t)b_k0 * N + bn) + b_c4;
    const float4* Bp1 = (const float4*)(B + (size_t)b_k1 * N + bn) + b_c4;

    int saw0 = ((a_c4 >> 1) * 8 + (a_row0 >> 4)) * 128 + (a_row0 & 7) * 16
               + ((a_row0 >> 3) & 1) + 2 * (a_c4 & 1);
    int saw1 = ((a_c4 >> 1) * 8 + (a_row1 >> 4)) * 128 + (a_row1 & 7) * 16
               + ((a_row1 >> 3) & 1) + 2 * (a_c4 & 1);
    int sbw0 = ((b_k0 >> 3) * 16 + (b_c4 >> 1)) * 64 + (b_c4 & 1) * 32
               + (b_k0 & 3) * 2 + ((b_k0 >> 2) & 1);
    int sbw1 = ((b_k1 >> 3) * 16 + (b_c4 >> 1)) * 64 + (b_c4 & 1) * 32
               + (b_k1 & 3) * 2 + ((b_k1 >> 2) & 1);

    int nt = K >> 4;
    size_t bstride = (size_t)4 * N;

    float4 av0 = Ap0[0], av1 = Ap1[0], bv0 = Bp0[0], bv1 = Bp1[0];
    stA_frag(sA[0], saw0, av0);
    stA_frag(sA[0], saw1, av1);
    stB_frag(sB[0], sbw0, bv0);
    stB_frag(sB[0], sbw1, bv1);
    __syncthreads();

    for (int kt = 0; kt < nt; kt++) {
        int cur = kt & 1;
        bool more = (kt + 1 < nt);
        if (more) {
            av0 = Ap0[(kt + 1) * 4];
            av1 = Ap1[(kt + 1) * 4];
            bv0 = Bp0[(size_t)(kt + 1) * bstride];
            bv1 = Bp1[(size_t)(kt + 1) * bstride];
        }
        #pragma unroll
        for (int ks = 0; ks < 2; ks++) {
            uint4 af[4];
            uint2 bf[4];
            #pragma unroll
            for (int mi = 0; mi < 4; mi++)
                af[mi] = *(const uint4*)&sA[cur][(ks * 8 + wm * 4 + mi) * 128 + lane * 4];
            #pragma unroll
            for (int ni = 0; ni < 4; ni++)
                bf[ni] = *(const uint2*)&sB[cur][(ks * 16 + wn * 4 + ni) * 64 + lane * 2];
            #pragma unroll
            for (int mi = 0; mi < 4; mi++)
                #pragma unroll
                for (int ni = 0; ni < 4; ni++)
                    mma_tf32(acc[mi][ni], &af[mi].x, &bf[ni].x);
        }
        if (more) {
            stA_frag(sA[cur ^ 1], saw0, av0);
            stA_frag(sA[cur ^ 1], saw1, av1);
            stB_frag(sB[cur ^ 1], sbw0, bv0);
            stB_frag(sB[cur ^ 1], sbw1, bv1);
        }
        __syncthreads();
    }

    #pragma unroll
    for (int ni = 0; ni < 4; ni++) {
        int col = bn + wn * 32 + ni * 8 + (lane & 3) * 2;
        float b0 = bias[col], b1 = bias[col + 1];
        #pragma unroll
        for (int mi = 0; mi < 4; mi++) {
            int r0 = bm + wm * 64 + mi * 16 + (lane >> 2);
            float v0 = acc[mi][ni][0] + b0;
            float v1 = acc[mi][ni][1] + b1;
            float v2 = acc[mi][ni][2] + b0;
            float v3 = acc[mi][ni][3] + b1;
            if (EPI == 1) {
                v0 = 0.5f * v0 * (1.f + erff(v0 * 0.70710678118654752f));
                v1 = 0.5f * v1 * (1.f + erff(v1 * 0.70710678118654752f));
                v2 = 0.5f * v2 * (1.f + erff(v2 * 0.70710678118654752f));
                v3 = 0.5f * v3 * (1.f + erff(v3 * 0.70710678118654752f));
            }
            if (EPI == 2) {
                float2 r0v = *(const float2*)&res[(size_t)r0 * N + col];
                float2 r1v = *(const float2*)&res[(size_t)(r0 + 8) * N + col];
                v0 += r0v.x; v1 += r0v.y; v2 += r1v.x; v3 += r1v.y;
            }
            float2 o0; o0.x = v0; o0.y = v1;
            float2 o1; o1.x = v2; o1.y = v3;
            *(float2*)&C[(size_t)r0 * N + col] = o0;
            *(float2*)&C[(size_t)(r0 + 8) * N + col] = o1;
        }
    }
}

template <int EPI>
__global__ void __launch_bounds__(256) gemm_tc(const float* __restrict__ A,
                                               const float* __restrict__ B,
                                               const float* __restrict__ bias,
                                               const float* __restrict__ res,
                                               float* __restrict__ C,
                                               int M, int N, int K) {
    gemm_core<EPI>(A, B, bias, res, C, M, N, K);
}

__global__ void __launch_bounds__(256) gemm_qkv(const float* __restrict__ A,
                                                const float* __restrict__ B0,
                                                const float* __restrict__ B1,
                                                const float* __restrict__ B2,
                                                const float* __restrict__ c0,
                                                const float* __restrict__ c1,
                                                const float* __restrict__ c2,
                                                float* __restrict__ O0,
                                                float* __restrict__ O1,
                                                float* __restrict__ O2,
                                                int M, int N, int K) {
    const float* B = (blockIdx.z == 0) ? B0 : (blockIdx.z == 1) ? B1 : B2;
    const float* bias = (blockIdx.z == 0) ? c0 : (blockIdx.z == 1) ? c1 : c2;
    float* C = (blockIdx.z == 0) ? O0 : (blockIdx.z == 1) ? O1 : O2;
    gemm_core<0>(A, B, bias, nullptr, C, M, N, K);
}

// ---------------- TF32 flash attention (causal) ----------------
__global__ void __launch_bounds__(128) attn_tc(const float* __restrict__ q,
                                               const float* __restrict__ k,
                                               const float* __restrict__ v,
                                               const int* __restrict__ amask,
                                               float* __restrict__ o) {
    __shared__ unsigned sQ[4096];   // [warp4][kstep8] A-frags (512B)
    __shared__ unsigned sK[4096];   // [kstep8][cfrag8] B-frags; aliased as P A-frags
    __shared__ unsigned sV[4096];   // [kstep8][nfrag8] B-frags

    int tid = threadIdx.x, lane = tid & 31, wid = tid >> 5;
    int head = blockIdx.y, qb = blockIdx.x;
    int hc = head * HDD;

    // pack Q (scaled 1/8) into A-frag layout: 64 rows x 16 float4 = 1024 fids
    #pragma unroll
    for (int it = 0; it < 8; it++) {
        int fid = tid + it * 128;
        int row = fid >> 4, c4 = fid & 15;
        float4 qv = *(const float4*)(q + (size_t)(qb * 64 + row) * DIM + hc + c4 * 4);
        int base = ((row >> 4) * 8 + (c4 >> 1)) * 128 + (row & 7) * 16
                   + ((row >> 3) & 1) + 2 * (c4 & 1);
        sQ[base]      = f2tf(qv.x * 0.125f);
        sQ[base + 4]  = f2tf(qv.y * 0.125f);
        sQ[base + 8]  = f2tf(qv.z * 0.125f);
        sQ[base + 12] = f2tf(qv.w * 0.125f);
    }

    float m0 = -1e30f, m1 = -1e30f, l0 = 0.f, l1 = 0.f;
    float oacc[8][4] = {};
    int r0g = qb * 64 + wid * 16 + (lane >> 2);

    for (int kb = 0; kb <= qb; kb++) {
        __syncthreads();   // previous iter done with sK(P)/sV
        // pack K and V tiles (64 rows x 16 float4 each = 1024 fids)
        #pragma unroll
        for (int it = 0; it < 8; it++) {
            int fid = tid + it * 128;
            int row = fid >> 4, c4 = fid & 15;
            float4 kv = *(const float4*)(k + (size_t)(kb * 64 + row) * DIM + hc + c4 * 4);
            int kbse = ((c4 >> 1) * 8 + (row >> 3)) * 64 + (row & 7) * 8 + (c4 & 1);
            sK[kbse]     = f2tf(kv.x);
            sK[kbse + 2] = f2tf(kv.y);
            sK[kbse + 4] = f2tf(kv.z);
            sK[kbse + 6] = f2tf(kv.w);
            float4 vv = *(const float4*)(v + (size_t)(kb * 64 + row) * DIM + hc + c4 * 4);
            int vbse = ((row >> 3) * 8 + (c4 >> 1)) * 64 + (c4 & 1) * 32
                       + (row & 3) * 2 + ((row >> 2) & 1);
            sV[vbse]      = f2tf(vv.x);
            sV[vbse + 8]  = f2tf(vv.y);
            sV[vbse + 16] = f2tf(vv.z);
            sV[vbse + 24] = f2tf(vv.w);
        }
        __syncthreads();

        // S = (Q/8) K^T
        float s[8][4] = {};
        #pragma unroll
        for (int ks = 0; ks < 8; ks++) {
            uint4 a = *(const uint4*)&sQ[(wid * 8 + ks) * 128 + lane * 4];
            #pragma unroll
            for (int nf = 0; nf < 8; nf++) {
                uint2 b = *(const uint2*)&sK[(ks * 8 + nf) * 64 + lane * 2];
                mma_tf32(s[nf], &a.x, &b.x);
            }
        }

        // masking
        bool diag = (kb == qb);
        #pragma unroll
        for (int nf = 0; nf < 8; nf++) {
            int c0 = kb * 64 + nf * 8 + (lane & 3) * 2;
            bool p0 = (amask[c0] == 0), p1 = (amask[c0 + 1] == 0);
            if ((diag && c0 > r0g) || p0)           s[nf][0] = -1e30f;
            if ((diag && c0 + 1 > r0g) || p1)       s[nf][1] = -1e30f;
            if ((diag && c0 > r0g + 8) || p0)       s[nf][2] = -1e30f;
            if ((diag && c0 + 1 > r0g + 8) || p1)   s[nf][3] = -1e30f;
        }

        // online softmax
        float mx0 = -1e30f, mx1 = -1e30f;
        #pragma unroll
        for (int nf = 0; nf < 8; nf++) {
            mx0 = fmaxf(mx0, fmaxf(s[nf][0], s[nf][1]));
            mx1 = fmaxf(mx1, fmaxf(s[nf][2], s[nf][3]));
        }
        mx0 = fmaxf(mx0, __shfl_xor_sync(0xffffffffu, mx0, 1));
        mx0 = fmaxf(mx0, __shfl_xor_sync(0xffffffffu, mx0, 2));
        mx1 = fmaxf(mx1, __shfl_xor_sync(0xffffffffu, mx1, 1));
        mx1 = fmaxf(mx1, __shfl_xor_sync(0xffffffffu, mx1, 2));
        float mn0 = fmaxf(m0, mx0), mn1 = fmaxf(m1, mx1);
        float f0 = __expf(m0 - mn0), f1 = __expf(m1 - mn1);
        float sum0 = 0.f, sum1 = 0.f;
        #pragma unroll
        for (int nf = 0; nf < 8; nf++) {
            s[nf][0] = __expf(s[nf][0] - mn0);
            s[nf][1] = __expf(s[nf][1] - mn0);
            s[nf][2] = __expf(s[nf][2] - mn1);
            s[nf][3] = __expf(s[nf][3] - mn1);
            sum0 += s[nf][0] + s[nf][1];
            sum1 += s[nf][2] + s[nf][3];
        }
        sum0 += __shfl_xor_sync(0xffffffffu, sum0, 1);
        sum0 += __shfl_xor_sync(0xffffffffu, sum0, 2);
        sum1 += __shfl_xor_sync(0xffffffffu, sum1, 1);
        sum1 += __shfl_xor_sync(0xffffffffu, sum1, 2);
        l0 = l0 * f0 + sum0;
        l1 = l1 * f1 + sum1;
        m0 = mn0; m1 = mn1;
        #pragma unroll
        for (int nf = 0; nf < 8; nf++) {
            oacc[nf][0] *= f0; oacc[nf][1] *= f0;
            oacc[nf][2] *= f1; oacc[nf][3] *= f1;
        }

        __syncthreads();   // all warps done reading sK as K

        // write P into sK (per-warp region) in A-frag layout
        {
            int q2 = (lane & 3) * 2;
            int lt0 = (lane >> 2) * 4 + (q2 & 3);
            int j0 = ((q2 >> 2) & 1) * 2;
            int lt1 = (lane >> 2) * 4 + ((q2 + 1) & 3);
            int j1 = (((q2 + 1) >> 2) & 1) * 2;
            #pragma unroll
            for (int nf = 0; nf < 8; nf++) {
                unsigned* pw = &sK[wid * 1024 + nf * 128];
                pw[lt0 * 4 + j0]     = f2tf(s[nf][0]);
                pw[lt1 * 4 + j1]     = f2tf(s[nf][1]);
                pw[lt0 * 4 + j0 + 1] = f2tf(s[nf][2]);
                pw[lt1 * 4 + j1 + 1] = f2tf(s[nf][3]);
            }
        }
        __syncwarp();

        // O += P V
        #pragma unroll
        for (int ks = 0; ks < 8; ks++) {
            uint4 a = *(const uint4*)&sK[wid * 1024 + ks * 128 + lane * 4];
            #pragma unroll
            for (int nf = 0; nf < 8; nf++) {
                uint2 b = *(const uint2*)&sV[(ks * 8 + nf) * 64 + lane * 2];
                mma_tf32(oacc[nf], &a.x, &b.x);
            }
        }
    }

    // epilogue
    float inv0 = 1.f / l0, inv1 = 1.f / l1;
    #pragma unroll
    for (int nf = 0; nf < 8; nf++) {
        int col = hc + nf * 8 + (lane & 3) * 2;
        float2 o0; o0.x = oacc[nf][0] * inv0; o0.y = oacc[nf][1] * inv0;
        float2 o1; o1.x = oacc[nf][2] * inv1; o1.y = oacc[nf][3] * inv1;
        *(float2*)&o[(size_t)r0g * DIM + col] = o0;
        *(float2*)&o[(size_t)(r0g + 8) * DIM + col] = o1;
    }
}

// ---------------- launch ----------------
extern "C" void kernel_launch(void* const* d_in, const int* in_sizes, int n_in,
                              void* d_out, int out_size) {
    const float* hs    = (const float*)d_in[0];
    const int*   amask = (const int*)d_in[1];
    const float* ln1w  = (const float*)d_in[2];
    const float* ln1b  = (const float*)d_in[3];
    const float* wq    = (const float*)d_in[4];
    const float* bq    = (const float*)d_in[5];
    const float* wk    = (const float*)d_in[6];
    const float* bk    = (const float*)d_in[7];
    const float* wv    = (const float*)d_in[8];
    const float* bv    = (const float*)d_in[9];
    const float* wo    = (const float*)d_in[10];
    const float* bo    = (const float*)d_in[11];
    const float* ln2w  = (const float*)d_in[12];
    const float* ln2b  = (const float*)d_in[13];
    const float* wup   = (const float*)d_in[14];
    const float* bup   = (const float*)d_in[15];
    const float* wdn   = (const float*)d_in[16];
    const float* bdn   = (const float*)d_in[17];

    float *x, *qb_, *kb_, *vb_, *attn, *hidden, *y, *ff;
    cudaGetSymbolAddress((void**)&x, g_x);
    cudaGetSymbolAddress((void**)&qb_, g_q);
    cudaGetSymbolAddress((void**)&kb_, g_k);
    cudaGetSymbolAddress((void**)&vb_, g_v);
    cudaGetSymbolAddress((void**)&attn, g_attn);
    cudaGetSymbolAddress((void**)&hidden, g_hidden);
    cudaGetSymbolAddress((void**)&y, g_y);
    cudaGetSymbolAddress((void**)&ff, g_ff);

    dim3 gD(DIM / 128, SEQ / 128);          // (6, 32)
    dim3 gQKV(DIM / 128, SEQ / 128, 3);     // (6, 32, 3)
    dim3 gF(FFD / 128, SEQ / 128);          // (24, 32)

    ln_kernel<<<SEQ, 256>>>(hs, ln1w, ln1b, x);
    gemm_qkv<<<gQKV, 256>>>(x, wq, wk, wv, bq, bk, bv, qb_, kb_, vb_, SEQ, DIM, DIM);
    attn_tc<<<dim3(SEQ / 64, NH), 128>>>(qb_, kb_, vb_, amask, attn);
    gemm_tc<2><<<gD, 256>>>(attn, wo, bo, hs, hidden, SEQ, DIM, DIM);
    ln_kernel<<<SEQ, 256>>>(hidden, ln2w, ln2b, y);
    gemm_tc<1><<<gF, 256>>>(y, wup, bup, nullptr, ff, SEQ, FFD, DIM);
    gemm_tc<2><<<gD, 256>>>(ff, wdn, bdn, hidden, (float*)d_out, SEQ, DIM, FFD);
}

// round 4
// speedup vs baseline: 1.4461x; 1.1302x over previous
#include <cuda_runtime.h>
#include <math.h>

#define SEQ 4096
#define DIM 768
#define NH  12
#define HDD 64
#define FFD 3072

// ---------------- scratch (device globals) ----------------
__device__ float g_x[SEQ * DIM];
__device__ float g_q[SEQ * DIM];
__device__ float g_k[SEQ * DIM];
__device__ float g_v[SEQ * DIM];
__device__ float g_attn[SEQ * DIM];
__device__ float g_hidden[SEQ * DIM];
__device__ float g_y[SEQ * DIM];
__device__ float g_ff[SEQ * FFD];

// ---------------- helpers ----------------
__device__ __forceinline__ unsigned f2tf(float f) {
    unsigned r;
    asm("cvt.rna.tf32.f32 %0, %1;" : "=r"(r) : "f"(f));
    return r;
}

__device__ __forceinline__ void mma_tf32(float* c, const unsigned* a, const unsigned* b) {
    asm volatile(
        "mma.sync.aligned.m16n8k8.row.col.f32.tf32.tf32.f32 "
        "{%0,%1,%2,%3}, {%4,%5,%6,%7}, {%8,%9}, {%0,%1,%2,%3};"
        : "+f"(c[0]), "+f"(c[1]), "+f"(c[2]), "+f"(c[3])
        : "r"(a[0]), "r"(a[1]), "r"(a[2]), "r"(a[3]), "r"(b[0]), "r"(b[1]));
}

__device__ __forceinline__ float block_sum_256(float v, float* red) {
    int lane = threadIdx.x & 31;
    int wid  = threadIdx.x >> 5;
    #pragma unroll
    for (int o = 16; o; o >>= 1) v += __shfl_xor_sync(0xffffffffu, v, o);
    if (lane == 0) red[wid] = v;
    __syncthreads();
    float r;
    if (wid == 0) {
        r = (lane < 8) ? red[lane] : 0.f;
        #pragma unroll
        for (int o = 4; o; o >>= 1) r += __shfl_xor_sync(0xffffffffu, r, o);
        if (lane == 0) red[0] = r;
    }
    __syncthreads();
    r = red[0];
    __syncthreads();
    return r;
}

// ---------------- LayerNorm ----------------
__global__ void __launch_bounds__(256) ln_kernel(const float* __restrict__ in,
                                                 const float* __restrict__ w,
                                                 const float* __restrict__ b,
                                                 float* __restrict__ out) {
    __shared__ float red[32];
    int row = blockIdx.x;
    const float* x = in + (size_t)row * DIM;
    int t = threadIdx.x;
    float v0 = x[t], v1 = x[t + 256], v2 = x[t + 512];
    float mu = block_sum_256(v0 + v1 + v2, red) * (1.f / DIM);
    float d0 = v0 - mu, d1 = v1 - mu, d2 = v2 - mu;
    float var = block_sum_256(d0 * d0 + d1 * d1 + d2 * d2, red) * (1.f / DIM);
    float rstd = rsqrtf(var + 1e-5f);
    float* o = out + (size_t)row * DIM;
    o[t]       = d0 * rstd * w[t]       + b[t];
    o[t + 256] = d1 * rstd * w[t + 256] + b[t + 256];
    o[t + 512] = d2 * rstd * w[t + 512] + b[t + 512];
}

// ---------------- TF32 tensor-core GEMM ----------------
__device__ __forceinline__ void stA_frag(unsigned* s, int base, float4 v) {
    s[base]      = f2tf(v.x);
    s[base + 4]  = f2tf(v.y);
    s[base + 8]  = f2tf(v.z);
    s[base + 12] = f2tf(v.w);
}
__device__ __forceinline__ void stB_frag(unsigned* s, int base, float4 v) {
    s[base]      = f2tf(v.x);
    s[base + 8]  = f2tf(v.y);
    s[base + 16] = f2tf(v.z);
    s[base + 24] = f2tf(v.w);
}

template <int EPI>
__device__ __forceinline__ void gemm_core(const float* __restrict__ A,
                                          const float* __restrict__ B,
                                          const float* __restrict__ bias,
                                          const float* __restrict__ res,
                                          float* __restrict__ C,
                                          int M, int N, int K) {
    __shared__ unsigned sA[2][2048];
    __shared__ unsigned sB[2][2048];
    int tid = threadIdx.x, lane = tid & 31, wid = tid >> 5;
    int wm = wid & 1, wn = wid >> 1;
    int bm = blockIdx.y * 128, bn = blockIdx.x * 128;

    float acc[4][4][4] = {};

    int a_row0 = tid >> 2, a_c4 = tid & 3;
    int a_row1 = a_row0 + 64;
    int b_k0 = tid >> 5, b_c4 = tid & 31;
    int b_k1 = b_k0 + 8;

    const float4* Ap0 = (const float4*)(A + (size_t)(bm + a_row0) * K) + a_c4;
    const float4* Ap1 = (const float4*)(A + (size_t)(bm + a_row1) * K) + a_c4;
    const float4* Bp0 = (const float4*)(B + (size_t)b_k0 * N + bn) + b_c4;
    const float4* Bp1 = (const float4*)(B + (size_t)b_k1 * N + bn) + b_c4;

    int saw0 = ((a_c4 >> 1) * 8 + (a_row0 >> 4)) * 128 + (a_row0 & 7) * 16
               + ((a_row0 >> 3) & 1) + 2 * (a_c4 & 1);
    int saw1 = ((a_c4 >> 1) * 8 + (a_row1 >> 4)) * 128 + (a_row1 & 7) * 16
               + ((a_row1 >> 3) & 1) + 2 * (a_c4 & 1);
    int sbw0 = ((b_k0 >> 3) * 16 + (b_c4 >> 1)) * 64 + (b_c4 & 1) * 32
               + (b_k0 & 3) * 2 + ((b_k0 >> 2) & 1);
    int sbw1 = ((b_k1 >> 3) * 16 + (b_c4 >> 1)) * 64 + (b_c4 & 1) * 32
               + (b_k1 & 3) * 2 + ((b_k1 >> 2) & 1);

    int nt = K >> 4;
    size_t bstride = (size_t)4 * N;

    float4 av0 = Ap0[0], av1 = Ap1[0], bv0 = Bp0[0], bv1 = Bp1[0];
    stA_frag(sA[0], saw0, av0);
    stA_frag(sA[0], saw1, av1);
    stB_frag(sB[0], sbw0, bv0);
    stB_frag(sB[0], sbw1, bv1);
    __syncthreads();

    for (int kt = 0; kt < nt; kt++) {
        int cur = kt & 1;
        bool more = (kt + 1 < nt);
        if (more) {
            av0 = Ap0[(kt + 1) * 4];
            av1 = Ap1[(kt + 1) * 4];
            bv0 = Bp0[(size_t)(kt + 1) * bstride];
            bv1 = Bp1[(size_t)(kt + 1) * bstride];
        }
        #pragma unroll
        for (int ks = 0; ks < 2; ks++) {
            uint4 af[4];
            uint2 bf[4];
            #pragma unroll
            for (int mi = 0; mi < 4; mi++)
                af[mi] = *(const uint4*)&sA[cur][(ks * 8 + wm * 4 + mi) * 128 + lane * 4];
            #pragma unroll
            for (int ni = 0; ni < 4; ni++)
                bf[ni] = *(const uint2*)&sB[cur][(ks * 16 + wn * 4 + ni) * 64 + lane * 2];
            #pragma unroll
            for (int mi = 0; mi < 4; mi++)
                #pragma unroll
                for (int ni = 0; ni < 4; ni++)
                    mma_tf32(acc[mi][ni], &af[mi].x, &bf[ni].x);
        }
        if (more) {
            stA_frag(sA[cur ^ 1], saw0, av0);
            stA_frag(sA[cur ^ 1], saw1, av1);
            stB_frag(sB[cur ^ 1], sbw0, bv0);
            stB_frag(sB[cur ^ 1], sbw1, bv1);
        }
        __syncthreads();
    }

    #pragma unroll
    for (int ni = 0; ni < 4; ni++) {
        int col = bn + wn * 32 + ni * 8 + (lane & 3) * 2;
        float b0 = bias[col], b1 = bias[col + 1];
        #pragma unroll
        for (int mi = 0; mi < 4; mi++) {
            int r0 = bm + wm * 64 + mi * 16 + (lane >> 2);
            float v0 = acc[mi][ni][0] + b0;
            float v1 = acc[mi][ni][1] + b1;
            float v2 = acc[mi][ni][2] + b0;
            float v3 = acc[mi][ni][3] + b1;
            if (EPI == 1) {
                v0 = 0.5f * v0 * (1.f + erff(v0 * 0.70710678118654752f));
                v1 = 0.5f * v1 * (1.f + erff(v1 * 0.70710678118654752f));
                v2 = 0.5f * v2 * (1.f + erff(v2 * 0.70710678118654752f));
                v3 = 0.5f * v3 * (1.f + erff(v3 * 0.70710678118654752f));
            }
            if (EPI == 2) {
                float2 r0v = *(const float2*)&res[(size_t)r0 * N + col];
                float2 r1v = *(const float2*)&res[(size_t)(r0 + 8) * N + col];
                v0 += r0v.x; v1 += r0v.y; v2 += r1v.x; v3 += r1v.y;
            }
            float2 o0; o0.x = v0; o0.y = v1;
            float2 o1; o1.x = v2; o1.y = v3;
            *(float2*)&C[(size_t)r0 * N + col] = o0;
            *(float2*)&C[(size_t)(r0 + 8) * N + col] = o1;
        }
    }
}

template <int EPI>
__global__ void __launch_bounds__(256, 2) gemm_tc(const float* __restrict__ A,
                                                  const float* __restrict__ B,
                                                  const float* __restrict__ bias,
                                                  const float* __restrict__ res,
                                                  float* __restrict__ C,
                                                  int M, int N, int K) {
    gemm_core<EPI>(A, B, bias, res, C, M, N, K);
}

__global__ void __launch_bounds__(256, 2) gemm_qkv(const float* __restrict__ A,
                                                   const float* __restrict__ B0,
                                                   const float* __restrict__ B1,
                                                   const float* __restrict__ B2,
                                                   const float* __restrict__ c0,
                                                   const float* __restrict__ c1,
                                                   const float* __restrict__ c2,
                                                   float* __restrict__ O0,
                                                   float* __restrict__ O1,
                                                   float* __restrict__ O2,
                                                   int M, int N, int K) {
    const float* B = (blockIdx.z == 0) ? B0 : (blockIdx.z == 1) ? B1 : B2;
    const float* bias = (blockIdx.z == 0) ? c0 : (blockIdx.z == 1) ? c1 : c2;
    float* C = (blockIdx.z == 0) ? O0 : (blockIdx.z == 1) ? O1 : O2;
    gemm_core<0>(A, B, bias, nullptr, C, M, N, K);
}

// ---------------- TF32 flash attention (causal), 8 warps, q-tile 128 ----------------
// dynamic smem: sQ 8192 u32 (A-frags, per warp) | sK 4096 (B-frags) | sV 4096 (B-frags)
__global__ void __launch_bounds__(256, 2) attn_tc(const float* __restrict__ q,
                                                  const float* __restrict__ k,
                                                  const float* __restrict__ v,
                                                  const int* __restrict__ amask,
                                                  float* __restrict__ o) {
    extern __shared__ unsigned smbuf[];
    unsigned* sQ = smbuf;            // 8192
    unsigned* sK = smbuf + 8192;     // 4096
    unsigned* sV = smbuf + 12288;    // 4096

    int tid = threadIdx.x, lane = tid & 31, wid = tid >> 5;
    int head = blockIdx.y;
    int qb = gridDim.x - 1 - blockIdx.x;   // heaviest blocks first
    int hc = head * HDD;
    int qrow0 = qb * 128;

    // pack Q (scaled 1/8): 128 rows x 16 float4 = 2048 fids
    #pragma unroll
    for (int it = 0; it < 8; it++) {
        int fid = tid + it * 256;
        int row = fid >> 4, c4 = fid & 15;
        float4 qv = *(const float4*)(q + (size_t)(qrow0 + row) * DIM + hc + c4 * 4);
        int base = ((row >> 4) * 8 + (c4 >> 1)) * 128 + (row & 7) * 16
                   + ((row >> 3) & 1) + 2 * (c4 & 1);
        sQ[base]      = f2tf(qv.x * 0.125f);
        sQ[base + 4]  = f2tf(qv.y * 0.125f);
        sQ[base + 8]  = f2tf(qv.z * 0.125f);
        sQ[base + 12] = f2tf(qv.w * 0.125f);
    }

    float m0 = -1e30f, m1 = -1e30f, l0 = 0.f, l1 = 0.f;
    float oacc[8][4] = {};
    int r0g = qrow0 + wid * 16 + (lane >> 2);

    // shuffle constants for P C-frag -> A-frag
    int srcA = (lane & ~3) | ((lane & 3) >> 1);
    int srcB = srcA | 2;
    bool sel = lane & 1;

    int nkb = 2 * qb + 2;
    for (int kb = 0; kb < nkb; kb++) {
        __syncthreads();   // previous iter done reading sK/sV
        // pack K,V tiles: 64 rows x 16 float4 = 1024 fids
        #pragma unroll
        for (int it = 0; it < 4; it++) {
            int fid = tid + it * 256;
            int row = fid >> 4, c4 = fid & 15;
            float4 kv = *(const float4*)(k + (size_t)(kb * 64 + row) * DIM + hc + c4 * 4);
            int kbse = ((c4 >> 1) * 8 + (row >> 3)) * 64 + (row & 7) * 8 + (c4 & 1);
            sK[kbse]     = f2tf(kv.x);
            sK[kbse + 2] = f2tf(kv.y);
            sK[kbse + 4] = f2tf(kv.z);
            sK[kbse + 6] = f2tf(kv.w);
            float4 vv = *(const float4*)(v + (size_t)(kb * 64 + row) * DIM + hc + c4 * 4);
            int vbse = ((row >> 3) * 8 + (c4 >> 1)) * 64 + (c4 & 1) * 32
                       + (row & 3) * 2 + ((row >> 2) & 1);
            sV[vbse]      = f2tf(vv.x);
            sV[vbse + 8]  = f2tf(vv.y);
            sV[vbse + 16] = f2tf(vv.z);
            sV[vbse + 24] = f2tf(vv.w);
        }
        __syncthreads();

        // S = (Q/8) K^T
        float s[8][4] = {};
        #pragma unroll
        for (int ks = 0; ks < 8; ks++) {
            uint4 a = *(const uint4*)&sQ[(wid * 8 + ks) * 128 + lane * 4];
            #pragma unroll
            for (int nf = 0; nf < 8; nf++) {
                uint2 b = *(const uint2*)&sK[(ks * 8 + nf) * 64 + lane * 2];
                mma_tf32(s[nf], &a.x, &b.x);
            }
        }

        // causal + pad masking (always-correct form)
        #pragma unroll
        for (int nf = 0; nf < 8; nf++) {
            int c0 = kb * 64 + nf * 8 + (lane & 3) * 2;
            bool p0 = (amask[c0] == 0), p1 = (amask[c0 + 1] == 0);
            if ((c0 > r0g) || p0)           s[nf][0] = -1e30f;
            if ((c0 + 1 > r0g) || p1)       s[nf][1] = -1e30f;
            if ((c0 > r0g + 8) || p0)       s[nf][2] = -1e30f;
            if ((c0 + 1 > r0g + 8) || p1)   s[nf][3] = -1e30f;
        }

        // online softmax (rows owned by quads of 4 lanes)
        float mx0 = -1e30f, mx1 = -1e30f;
        #pragma unroll
        for (int nf = 0; nf < 8; nf++) {
            mx0 = fmaxf(mx0, fmaxf(s[nf][0], s[nf][1]));
            mx1 = fmaxf(mx1, fmaxf(s[nf][2], s[nf][3]));
        }
        mx0 = fmaxf(mx0, __shfl_xor_sync(0xffffffffu, mx0, 1));
        mx0 = fmaxf(mx0, __shfl_xor_sync(0xffffffffu, mx0, 2));
        mx1 = fmaxf(mx1, __shfl_xor_sync(0xffffffffu, mx1, 1));
        mx1 = fmaxf(mx1, __shfl_xor_sync(0xffffffffu, mx1, 2));
        float mn0 = fmaxf(m0, mx0), mn1 = fmaxf(m1, mx1);
        float f0 = __expf(m0 - mn0), f1 = __expf(m1 - mn1);
        float sum0 = 0.f, sum1 = 0.f;
        #pragma unroll
        for (int nf = 0; nf < 8; nf++) {
            s[nf][0] = __expf(s[nf][0] - mn0);
            s[nf][1] = __expf(s[nf][1] - mn0);
            s[nf][2] = __expf(s[nf][2] - mn1);
            s[nf][3] = __expf(s[nf][3] - mn1);
            sum0 += s[nf][0] + s[nf][1];
            sum1 += s[nf][2] + s[nf][3];
        }
        sum0 += __shfl_xor_sync(0xffffffffu, sum0, 1);
        sum0 += __shfl_xor_sync(0xffffffffu, sum0, 2);
        sum1 += __shfl_xor_sync(0xffffffffu, sum1, 1);
        sum1 += __shfl_xor_sync(0xffffffffu, sum1, 2);
        l0 = l0 * f0 + sum0;
        l1 = l1 * f1 + sum1;
        m0 = mn0; m1 = mn1;
        #pragma unroll
        for (int nf = 0; nf < 8; nf++) {
            oacc[nf][0] *= f0; oacc[nf][1] *= f0;
            oacc[nf][2] *= f1; oacc[nf][3] *= f1;
        }

        // O += P V : rebuild P A-frags via quad shuffles (no smem round-trip)
        #pragma unroll
        for (int ks = 0; ks < 8; ks++) {
            float t0 = __shfl_sync(0xffffffffu, s[ks][0], srcA);
            float t1 = __shfl_sync(0xffffffffu, s[ks][1], srcA);
            float t2 = __shfl_sync(0xffffffffu, s[ks][2], srcA);
            float t3 = __shfl_sync(0xffffffffu, s[ks][3], srcA);
            float u0 = __shfl_sync(0xffffffffu, s[ks][0], srcB);
            float u1 = __shfl_sync(0xffffffffu, s[ks][1], srcB);
            float u2 = __shfl_sync(0xffffffffu, s[ks][2], srcB);
            float u3 = __shfl_sync(0xffffffffu, s[ks][3], srcB);
            unsigned a[4];
            a[0] = f2tf(sel ? t1 : t0);
            a[1] = f2tf(sel ? t3 : t2);
            a[2] = f2tf(sel ? u1 : u0);
            a[3] = f2tf(sel ? u3 : u2);
            #pragma unroll
            for (int nf = 0; nf < 8; nf++) {
                uint2 b = *(const uint2*)&sV[(ks * 8 + nf) * 64 + lane * 2];
                mma_tf32(oacc[nf], a, &b.x);
            }
        }
    }

    // epilogue
    float inv0 = 1.f / l0, inv1 = 1.f / l1;
    #pragma unroll
    for (int nf = 0; nf < 8; nf++) {
        int col = hc + nf * 8 + (lane & 3) * 2;
        float2 o0; o0.x = oacc[nf][0] * inv0; o0.y = oacc[nf][1] * inv0;
        float2 o1; o1.x = oacc[nf][2] * inv1; o1.y = oacc[nf][3] * inv1;
        *(float2*)&o[(size_t)r0g * DIM + col] = o0;
        *(float2*)&o[(size_t)(r0g + 8) * DIM + col] = o1;
    }
}

// ---------------- launch ----------------
extern "C" void kernel_launch(void* const* d_in, const int* in_sizes, int n_in,
                              void* d_out, int out_size) {
    const float* hs    = (const float*)d_in[0];
    const int*   amask = (const int*)d_in[1];
    const float* ln1w  = (const float*)d_in[2];
    const float* ln1b  = (const float*)d_in[3];
    const float* wq    = (const float*)d_in[4];
    const float* bq    = (const float*)d_in[5];
    const float* wk    = (const float*)d_in[6];
    const float* bk    = (const float*)d_in[7];
    const float* wv    = (const float*)d_in[8];
    const float* bv    = (const float*)d_in[9];
    const float* wo    = (const float*)d_in[10];
    const float* bo    = (const float*)d_in[11];
    const float* ln2w  = (const float*)d_in[12];
    const float* ln2b  = (const float*)d_in[13];
    const float* wup   = (const float*)d_in[14];
    const float* bup   = (const float*)d_in[15];
    const float* wdn   = (const float*)d_in[16];
    const float* bdn   = (const float*)d_in[17];

    float *x, *qb_, *kb_, *vb_, *attn, *hidden, *y, *ff;
    cudaGetSymbolAddress((void**)&x, g_x);
    cudaGetSymbolAddress((void**)&qb_, g_q);
    cudaGetSymbolAddress((void**)&kb_, g_k);
    cudaGetSymbolAddress((void**)&vb_, g_v);
    cudaGetSymbolAddress((void**)&attn, g_attn);
    cudaGetSymbolAddress((void**)&hidden, g_hidden);
    cudaGetSymbolAddress((void**)&y, g_y);
    cudaGetSymbolAddress((void**)&ff, g_ff);

    static int smem_set = 0;
    if (!smem_set) {
        cudaFuncSetAttribute(attn_tc, cudaFuncAttributeMaxDynamicSharedMemorySize, 65536);
        smem_set = 1;
    }

    dim3 gD(DIM / 128, SEQ / 128);          // (6, 32)
    dim3 gQKV(DIM / 128, SEQ / 128, 3);     // (6, 32, 3)
    dim3 gF(FFD / 128, SEQ / 128);          // (24, 32)

    ln_kernel<<<SEQ, 256>>>(hs, ln1w, ln1b, x);
    gemm_qkv<<<gQKV, 256>>>(x, wq, wk, wv, bq, bk, bv, qb_, kb_, vb_, SEQ, DIM, DIM);
    attn_tc<<<dim3(SEQ / 128, NH), 256, 65536>>>(qb_, kb_, vb_, amask, attn);
    gemm_tc<2><<<gD, 256>>>(attn, wo, bo, hs, hidden, SEQ, DIM, DIM);
    ln_kernel<<<SEQ, 256>>>(hidden, ln2w, ln2b, y);
    gemm_tc<1><<<gF, 256>>>(y, wup, bup, nullptr, ff, SEQ, FFD, DIM);
    gemm_tc<2><<<gD, 256>>>(ff, wdn, bdn, hidden, (float*)d_out, SEQ, DIM, FFD);
}

// round 5
// speedup vs baseline: 1.7919x; 1.2391x over previous
#include <cuda_runtime.h>
#include <math.h>

#define SEQ 4096
#define DIM 768
#define NH  12
#define HDD 64
#define FFD 3072

// ---------------- scratch (device globals) ----------------
__device__ float g_x[SEQ * DIM];
__device__ float g_q[SEQ * DIM];
__device__ float g_k[SEQ * DIM];
__device__ float g_v[SEQ * DIM];
__device__ float g_attn[SEQ * DIM];
__device__ float g_hidden[SEQ * DIM];
__device__ float g_y[SEQ * DIM];
__device__ float g_ff[SEQ * FFD];
__device__ unsigned g_kp[SEQ * DIM];   // K tiles pre-packed in mma B-frag layout
__device__ unsigned g_vp[SEQ * DIM];   // V tiles pre-packed in mma B-frag layout

// ---------------- helpers ----------------
__device__ __forceinline__ void mma_tf32(float* c, const unsigned* a, const unsigned* b) {
    asm volatile(
        "mma.sync.aligned.m16n8k8.row.col.f32.tf32.tf32.f32 "
        "{%0,%1,%2,%3}, {%4,%5,%6,%7}, {%8,%9}, {%0,%1,%2,%3};"
        : "+f"(c[0]), "+f"(c[1]), "+f"(c[2]), "+f"(c[3])
        : "r"(a[0]), "r"(a[1]), "r"(a[2]), "r"(a[3]), "r"(b[0]), "r"(b[1]));
}

__device__ __forceinline__ void cpa16(void* smem, const void* gmem) {
    unsigned saddr = (unsigned)__cvta_generic_to_shared(smem);
    asm volatile("cp.async.cg.shared.global [%0], [%1], 16;" :: "r"(saddr), "l"(gmem));
}
__device__ __forceinline__ void cpa_commit() { asm volatile("cp.async.commit_group;"); }
__device__ __forceinline__ void cpa_wait0() { asm volatile("cp.async.wait_group 0;"); }

__device__ __forceinline__ float block_sum_256(float v, float* red) {
    int lane = threadIdx.x & 31;
    int wid  = threadIdx.x >> 5;
    #pragma unroll
    for (int o = 16; o; o >>= 1) v += __shfl_xor_sync(0xffffffffu, v, o);
    if (lane == 0) red[wid] = v;
    __syncthreads();
    float r;
    if (wid == 0) {
        r = (lane < 8) ? red[lane] : 0.f;
        #pragma unroll
        for (int o = 4; o; o >>= 1) r += __shfl_xor_sync(0xffffffffu, r, o);
        if (lane == 0) red[0] = r;
    }
    __syncthreads();
    r = red[0];
    __syncthreads();
    return r;
}

// ---------------- LayerNorm ----------------
__global__ void __launch_bounds__(256) ln_kernel(const float* __restrict__ in,
                                                 const float* __restrict__ w,
                                                 const float* __restrict__ b,
                                                 float* __restrict__ out) {
    __shared__ float red[32];
    int row = blockIdx.x;
    const float* x = in + (size_t)row * DIM;
    int t = threadIdx.x;
    float v0 = x[t], v1 = x[t + 256], v2 = x[t + 512];
    float mu = block_sum_256(v0 + v1 + v2, red) * (1.f / DIM);
    float d0 = v0 - mu, d1 = v1 - mu, d2 = v2 - mu;
    float var = block_sum_256(d0 * d0 + d1 * d1 + d2 * d2, red) * (1.f / DIM);
    float rstd = rsqrtf(var + 1e-5f);
    float* o = out + (size_t)row * DIM;
    o[t]       = d0 * rstd * w[t]       + b[t];
    o[t + 256] = d1 * rstd * w[t + 256] + b[t + 256];
    o[t + 512] = d2 * rstd * w[t + 512] + b[t + 512];
}

// ---------------- TF32 tensor-core GEMM (raw fp32 bits as tf32) ----------------
__device__ __forceinline__ void stA_raw(unsigned* s, int base, float4 v) {
    s[base]      = __float_as_uint(v.x);
    s[base + 4]  = __float_as_uint(v.y);
    s[base + 8]  = __float_as_uint(v.z);
    s[base + 12] = __float_as_uint(v.w);
}
__device__ __forceinline__ void stB_raw(unsigned* s, int base, float4 v) {
    s[base]      = __float_as_uint(v.x);
    s[base + 8]  = __float_as_uint(v.y);
    s[base + 16] = __float_as_uint(v.z);
    s[base + 24] = __float_as_uint(v.w);
}

// block tile 128 x BN (BN = 128 or 64), 256 threads, K-tile 16, frag-packed smem
template <int EPI, int BN>
__device__ __forceinline__ void gemm_core(const float* __restrict__ A,
                                          const float* __restrict__ B,
                                          const float* __restrict__ bias,
                                          const float* __restrict__ res,
                                          float* __restrict__ C,
                                          int M, int N, int K) {
    constexpr int NFR = BN / 8;            // B frags per ks-step
    constexpr int BKF4 = BN / 4;           // float4 per B row
    constexpr int BPASS = BN / 64;         // B load passes (2 or 1)
    constexpr int BSTEP = 256 / BKF4;      // k-rows per pass
    constexpr int MI = (BN == 128) ? 4 : 2;

    __shared__ unsigned sA[2][2048];
    __shared__ unsigned sB[2][BN * 16];

    int tid = threadIdx.x, lane = tid & 31, wid = tid >> 5;
    int wm = (BN == 128) ? (wid & 1) : (wid & 3);
    int wn = (BN == 128) ? (wid >> 1) : (wid >> 2);
    int bm = blockIdx.y * 128, bn = blockIdx.x * BN;

    float acc[MI][4][4] = {};

    int a_row0 = tid >> 2, a_c4 = tid & 3;
    int a_row1 = a_row0 + 64;
    const float4* Ap0 = (const float4*)(A + (size_t)(bm + a_row0) * K) + a_c4;
    const float4* Ap1 = (const float4*)(A + (size_t)(bm + a_row1) * K) + a_c4;
    int saw0 = ((a_c4 >> 1) * 8 + (a_row0 >> 4)) * 128 + (a_row0 & 7) * 16
               + ((a_row0 >> 3) & 1) + 2 * (a_c4 & 1);
    int saw1 = ((a_c4 >> 1) * 8 + (a_row1 >> 4)) * 128 + (a_row1 & 7) * 16
               + ((a_row1 >> 3) & 1) + 2 * (a_c4 & 1);

    int b_k0 = tid / BKF4, b_c4 = tid % BKF4;
    const float4* Bp[BPASS];
    int sbw[BPASS];
    #pragma unroll
    for (int p = 0; p < BPASS; p++) {
        int kk = b_k0 + p * BSTEP;
        Bp[p] = (const float4*)(B + (size_t)kk * N + bn) + b_c4;
        sbw[p] = ((kk >> 3) * NFR + (b_c4 >> 1)) * 64 + (b_c4 & 1) * 32
                 + (kk & 3) * 2 + ((kk >> 2) & 1);
    }

    int nt = K >> 4;
    size_t bstride = (size_t)4 * N;

    float4 av0 = Ap0[0], av1 = Ap1[0], bv[BPASS];
    #pragma unroll
    for (int p = 0; p < BPASS; p++) bv[p] = Bp[p][0];
    stA_raw(sA[0], saw0, av0);
    stA_raw(sA[0], saw1, av1);
    #pragma unroll
    for (int p = 0; p < BPASS; p++) stB_raw(sB[0], sbw[p], bv[p]);
    __syncthreads();

    for (int kt = 0; kt < nt; kt++) {
        int cur = kt & 1;
        bool more = (kt + 1 < nt);
        if (more) {
            av0 = Ap0[(kt + 1) * 4];
            av1 = Ap1[(kt + 1) * 4];
            #pragma unroll
            for (int p = 0; p < BPASS; p++) bv[p] = Bp[p][(size_t)(kt + 1) * bstride];
        }
        #pragma unroll
        for (int ks = 0; ks < 2; ks++) {
            uint4 af[MI];
            uint2 bf[4];
            #pragma unroll
            for (int mi = 0; mi < MI; mi++)
                af[mi] = *(const uint4*)&sA[cur][(ks * 8 + wm * MI + mi) * 128 + lane * 4];
            #pragma unroll
            for (int ni = 0; ni < 4; ni++)
                bf[ni] = *(const uint2*)&sB[cur][(ks * NFR + wn * 4 + ni) * 64 + lane * 2];
            #pragma unroll
            for (int mi = 0; mi < MI; mi++)
                #pragma unroll
                for (int ni = 0; ni < 4; ni++)
                    mma_tf32(acc[mi][ni], &af[mi].x, &bf[ni].x);
        }
        if (more) {
            stA_raw(sA[cur ^ 1], saw0, av0);
            stA_raw(sA[cur ^ 1], saw1, av1);
            #pragma unroll
            for (int p = 0; p < BPASS; p++) stB_raw(sB[cur ^ 1], sbw[p], bv[p]);
        }
        __syncthreads();
    }

    #pragma unroll
    for (int ni = 0; ni < 4; ni++) {
        int col = bn + wn * 32 + ni * 8 + (lane & 3) * 2;
        float b0 = bias[col], b1 = bias[col + 1];
        #pragma unroll
        for (int mi = 0; mi < MI; mi++) {
            int r0 = bm + wm * (16 * MI) + mi * 16 + (lane >> 2);
            float v0 = acc[mi][ni][0] + b0;
            float v1 = acc[mi][ni][1] + b1;
            float v2 = acc[mi][ni][2] + b0;
            float v3 = acc[mi][ni][3] + b1;
            if (EPI == 1) {
                v0 = 0.5f * v0 * (1.f + erff(v0 * 0.70710678118654752f));
                v1 = 0.5f * v1 * (1.f + erff(v1 * 0.70710678118654752f));
                v2 = 0.5f * v2 * (1.f + erff(v2 * 0.70710678118654752f));
                v3 = 0.5f * v3 * (1.f + erff(v3 * 0.70710678118654752f));
            }
            if (EPI == 2) {
                float2 r0v = *(const float2*)&res[(size_t)r0 * N + col];
                float2 r1v = *(const float2*)&res[(size_t)(r0 + 8) * N + col];
                v0 += r0v.x; v1 += r0v.y; v2 += r1v.x; v3 += r1v.y;
            }
            float2 o0; o0.x = v0; o0.y = v1;
            float2 o1; o1.x = v2; o1.y = v3;
            *(float2*)&C[(size_t)r0 * N + col] = o0;
            *(float2*)&C[(size_t)(r0 + 8) * N + col] = o1;
        }
    }
}

template <int EPI, int BN>
__global__ void __launch_bounds__(256, 2) gemm_tc(const float* __restrict__ A,
                                                  const float* __restrict__ B,
                                                  const float* __restrict__ bias,
                                                  const float* __restrict__ res,
                                                  float* __restrict__ C,
                                                  int M, int N, int K) {
    gemm_core<EPI, BN>(A, B, bias, res, C, M, N, K);
}

__global__ void __launch_bounds__(256, 2) gemm_qkv(const float* __restrict__ A,
                                                   const float* __restrict__ B0,
                                                   const float* __restrict__ B1,
                                                   const float* __restrict__ B2,
                                                   const float* __restrict__ c0,
                                                   const float* __restrict__ c1,
                                                   const float* __restrict__ c2,
                                                   float* __restrict__ O0,
                                                   float* __restrict__ O1,
                                                   float* __restrict__ O2,
                                                   int M, int N, int K) {
    const float* B = (blockIdx.z == 0) ? B0 : (blockIdx.z == 1) ? B1 : B2;
    const float* bias = (blockIdx.z == 0) ? c0 : (blockIdx.z == 1) ? c1 : c2;
    float* C = (blockIdx.z == 0) ? O0 : (blockIdx.z == 1) ? O1 : O2;
    gemm_core<0, 128>(A, B, bias, nullptr, C, M, N, K);
}

// ---------------- pre-pack K/V tiles into mma B-frag layout ----------------
__global__ void __launch_bounds__(256) pack_kv(const float* __restrict__ k,
                                               const float* __restrict__ v,
                                               unsigned* __restrict__ kp,
                                               unsigned* __restrict__ vp) {
    int kb = blockIdx.x, head = blockIdx.y, tid = threadIdx.x;
    int hc = head * HDD;
    size_t base = ((size_t)head * (SEQ / 64) + kb) * 4096;
    #pragma unroll
    for (int it = 0; it < 4; it++) {
        int fid = tid + it * 256;
        int row = fid >> 4, c4 = fid & 15;
        float4 kv = *(const float4*)(k + (size_t)(kb * 64 + row) * DIM + hc + c4 * 4);
        int kbse = ((c4 >> 1) * 8 + (row >> 3)) * 64 + (row & 7) * 8 + (c4 & 1);
        kp[base + kbse]     = __float_as_uint(kv.x);
        kp[base + kbse + 2] = __float_as_uint(kv.y);
        kp[base + kbse + 4] = __float_as_uint(kv.z);
        kp[base + kbse + 6] = __float_as_uint(kv.w);
        float4 vv = *(const float4*)(v + (size_t)(kb * 64 + row) * DIM + hc + c4 * 4);
        int vbse = ((row >> 3) * 8 + (c4 >> 1)) * 64 + (c4 & 1) * 32
                   + (row & 3) * 2 + ((row >> 2) & 1);
        vp[base + vbse]      = __float_as_uint(vv.x);
        vp[base + vbse + 8]  = __float_as_uint(vv.y);
        vp[base + vbse + 16] = __float_as_uint(vv.z);
        vp[base + vbse + 24] = __float_as_uint(vv.w);
    }
}

// ---------------- TF32 flash attention, 8 warps, q-tile 128, cp.async pipelined ----
// smem u32: sQ[8192] | sK[2][4096] | sV[2][4096] | sMask[2][64]
__global__ void __launch_bounds__(256, 2) attn_tc(const float* __restrict__ q,
                                                  const unsigned* __restrict__ kp,
                                                  const unsigned* __restrict__ vp,
                                                  const int* __restrict__ amask,
                                                  float* __restrict__ o) {
    extern __shared__ unsigned smbuf[];
    unsigned* sQ = smbuf;                 // 8192
    unsigned* sK = smbuf + 8192;          // 2 x 4096
    unsigned* sV = smbuf + 16384;         // 2 x 4096
    int* sMask = (int*)(smbuf + 24576);   // 2 x 64

    int tid = threadIdx.x, lane = tid & 31, wid = tid >> 5;
    int head = blockIdx.y;
    int qb = gridDim.x - 1 - blockIdx.x;   // heaviest blocks first
    int hc = head * HDD;
    int qrow0 = qb * 128;

    // pack Q (scaled 1/8, raw bits): 128 rows x 16 float4
    #pragma unroll
    for (int it = 0; it < 8; it++) {
        int fid = tid + it * 256;
        int row = fid >> 4, c4 = fid & 15;
        float4 qv = *(const float4*)(q + (size_t)(qrow0 + row) * DIM + hc + c4 * 4);
        int base = ((row >> 4) * 8 + (c4 >> 1)) * 128 + (row & 7) * 16
                   + ((row >> 3) & 1) + 2 * (c4 & 1);
        sQ[base]      = __float_as_uint(qv.x * 0.125f);
        sQ[base + 4]  = __float_as_uint(qv.y * 0.125f);
        sQ[base + 8]  = __float_as_uint(qv.z * 0.125f);
        sQ[base + 12] = __float_as_uint(qv.w * 0.125f);
    }

    int nkb = 2 * qb + 2;
    // prologue: prefetch kb=0 into buffer 0, stage mask 0
    {
        size_t tb = ((size_t)head * (SEQ / 64) + 0) * 4096;
        const uint4* kg = (const uint4*)(kp + tb);
        const uint4* vg = (const uint4*)(vp + tb);
        #pragma unroll
        for (int it = 0; it < 4; it++) {
            int i = tid + it * 256;
            cpa16(&((uint4*)sK)[i], &kg[i]);
            cpa16(&((uint4*)sV)[i], &vg[i]);
        }
        cpa_commit();
        if (tid < 64) sMask[tid] = amask[tid];
    }

    float m0 = -1e30f, m1 = -1e30f, l0 = 0.f, l1 = 0.f;
    float oacc[8][4] = {};
    int r0g = qrow0 + wid * 16 + (lane >> 2);

    int srcA = (lane & ~3) | ((lane & 3) >> 1);
    int srcB = srcA | 2;
    bool sel = lane & 1;

    for (int kb = 0; kb < nkb; kb++) {
        int cur = kb & 1;
        cpa_wait0();
        __syncthreads();   // tile cur ready; all threads done with buffer cur^1

        if (kb + 1 < nkb) {
            size_t tb = ((size_t)head * (SEQ / 64) + (kb + 1)) * 4096;
            const uint4* kg = (const uint4*)(kp + tb);
            const uint4* vg = (const uint4*)(vp + tb);
            uint4* dk = (uint4*)(sK + (cur ^ 1) * 4096);
            uint4* dv = (uint4*)(sV + (cur ^ 1) * 4096);
            #pragma unroll
            for (int it = 0; it < 4; it++) {
                int i = tid + it * 256;
                cpa16(&dk[i], &kg[i]);
                cpa16(&dv[i], &vg[i]);
            }
            cpa_commit();
            if (tid < 64) sMask[(cur ^ 1) * 64 + tid] = amask[(kb + 1) * 64 + tid];
        }

        const unsigned* cK = sK + cur * 4096;
        const unsigned* cV = sV + cur * 4096;
        const int* cM = sMask + cur * 64;

        // S = (Q/8) K^T
        float s[8][4] = {};
        #pragma unroll
        for (int ks = 0; ks < 8; ks++) {
            uint4 a = *(const uint4*)&sQ[(wid * 8 + ks) * 128 + lane * 4];
            #pragma unroll
            for (int nf = 0; nf < 8; nf++) {
                uint2 b = *(const uint2*)&cK[(ks * 8 + nf) * 64 + lane * 2];
                mma_tf32(s[nf], &a.x, &b.x);
            }
        }

        // causal + pad masking
        #pragma unroll
        for (int nf = 0; nf < 8; nf++) {
            int cl = nf * 8 + (lane & 3) * 2;
            int c0 = kb * 64 + cl;
            bool p0 = (cM[cl] == 0), p1 = (cM[cl + 1] == 0);
            if ((c0 > r0g) || p0)           s[nf][0] = -1e30f;
            if ((c0 + 1 > r0g) || p1)       s[nf][1] = -1e30f;
            if ((c0 > r0g + 8) || p0)       s[nf][2] = -1e30f;
            if ((c0 + 1 > r0g + 8) || p1)   s[nf][3] = -1e30f;
        }

        // online softmax
        float mx0 = -1e30f, mx1 = -1e30f;
        #pragma unroll
        for (int nf = 0; nf < 8; nf++) {
            mx0 = fmaxf(mx0, fmaxf(s[nf][0], s[nf][1]));
            mx1 = fmaxf(mx1, fmaxf(s[nf][2], s[nf][3]));
        }
        mx0 = fmaxf(mx0, __shfl_xor_sync(0xffffffffu, mx0, 1));
        mx0 = fmaxf(mx0, __shfl_xor_sync(0xffffffffu, mx0, 2));
        mx1 = fmaxf(mx1, __shfl_xor_sync(0xffffffffu, mx1, 1));
        mx1 = fmaxf(mx1, __shfl_xor_sync(0xffffffffu, mx1, 2));
        float mn0 = fmaxf(m0, mx0), mn1 = fmaxf(m1, mx1);
        float f0 = __expf(m0 - mn0), f1 = __expf(m1 - mn1);
        float sum0 = 0.f, sum1 = 0.f;
        #pragma unroll
        for (int nf = 0; nf < 8; nf++) {
            s[nf][0] = __expf(s[nf][0] - mn0);
            s[nf][1] = __expf(s[nf][1] - mn0);
            s[nf][2] = __expf(s[nf][2] - mn1);
            s[nf][3] = __expf(s[nf][3] - mn1);
            sum0 += s[nf][0] + s[nf][1];
            sum1 += s[nf][2] + s[nf][3];
        }
        sum0 += __shfl_xor_sync(0xffffffffu, sum0, 1);
        sum0 += __shfl_xor_sync(0xffffffffu, sum0, 2);
        sum1 += __shfl_xor_sync(0xffffffffu, sum1, 1);
        sum1 += __shfl_xor_sync(0xffffffffu, sum1, 2);
        l0 = l0 * f0 + sum0;
        l1 = l1 * f1 + sum1;
        m0 = mn0; m1 = mn1;
        #pragma unroll
        for (int nf = 0; nf < 8; nf++) {
            oacc[nf][0] *= f0; oacc[nf][1] *= f0;
            oacc[nf][2] *= f1; oacc[nf][3] *= f1;
        }

        // O += P V : rebuild P A-frags via quad shuffles
        #pragma unroll
        for (int ks = 0; ks < 8; ks++) {
            float t0 = __shfl_sync(0xffffffffu, s[ks][0], srcA);
            float t1 = __shfl_sync(0xffffffffu, s[ks][1], srcA);
            float t2 = __shfl_sync(0xffffffffu, s[ks][2], srcA);
            float t3 = __shfl_sync(0xffffffffu, s[ks][3], srcA);
            float u0 = __shfl_sync(0xffffffffu, s[ks][0], srcB);
            float u1 = __shfl_sync(0xffffffffu, s[ks][1], srcB);
            float u2 = __shfl_sync(0xffffffffu, s[ks][2], srcB);
            float u3 = __shfl_sync(0xffffffffu, s[ks][3], srcB);
            unsigned a[4];
            a[0] = __float_as_uint(sel ? t1 : t0);
            a[1] = __float_as_uint(sel ? t3 : t2);
            a[2] = __float_as_uint(sel ? u1 : u0);
            a[3] = __float_as_uint(sel ? u3 : u2);
            #pragma unroll
            for (int nf = 0; nf < 8; nf++) {
                uint2 b = *(const uint2*)&cV[(ks * 8 + nf) * 64 + lane * 2];
                mma_tf32(oacc[nf], a, &b.x);
            }
        }
    }

    // epilogue
    float inv0 = 1.f / l0, inv1 = 1.f / l1;
    #pragma unroll
    for (int nf = 0; nf < 8; nf++) {
        int col = hc + nf * 8 + (lane & 3) * 2;
        float2 o0; o0.x = oacc[nf][0] * inv0; o0.y = oacc[nf][1] * inv0;
        float2 o1; o1.x = oacc[nf][2] * inv1; o1.y = oacc[nf][3] * inv1;
        *(float2*)&o[(size_t)r0g * DIM + col] = o0;
        *(float2*)&o[(size_t)(r0g + 8) * DIM + col] = o1;
    }
}

#define ATTN_SMEM ((24576 + 128) * 4)

// ---------------- launch ----------------
extern "C" void kernel_launch(void* const* d_in, const int* in_sizes, int n_in,
                              void* d_out, int out_size) {
    const float* hs    = (const float*)d_in[0];
    const int*   amask = (const int*)d_in[1];
    const float* ln1w  = (const float*)d_in[2];
    const float* ln1b  = (const float*)d_in[3];
    const float* wq    = (const float*)d_in[4];
    const float* bq    = (const float*)d_in[5];
    const float* wk    = (const float*)d_in[6];
    const float* bk    = (const float*)d_in[7];
    const float* wv    = (const float*)d_in[8];
    const float* bv    = (const float*)d_in[9];
    const float* wo    = (const float*)d_in[10];
    const float* bo    = (const float*)d_in[11];
    const float* ln2w  = (const float*)d_in[12];
    const float* ln2b  = (const float*)d_in[13];
    const float* wup   = (const float*)d_in[14];
    const float* bup   = (const float*)d_in[15];
    const float* wdn   = (const float*)d_in[16];
    const float* bdn   = (const float*)d_in[17];

    float *x, *qb_, *kb_, *vb_, *attn, *hidden, *y, *ff;
    unsigned *kpk, *vpk;
    cudaGetSymbolAddress((void**)&x, g_x);
    cudaGetSymbolAddress((void**)&qb_, g_q);
    cudaGetSymbolAddress((void**)&kb_, g_k);
    cudaGetSymbolAddress((void**)&vb_, g_v);
    cudaGetSymbolAddress((void**)&attn, g_attn);
    cudaGetSymbolAddress((void**)&hidden, g_hidden);
    cudaGetSymbolAddress((void**)&y, g_y);
    cudaGetSymbolAddress((void**)&ff, g_ff);
    cudaGetSymbolAddress((void**)&kpk, g_kp);
    cudaGetSymbolAddress((void**)&vpk, g_vp);

    static int smem_set = 0;
    if (!smem_set) {
        cudaFuncSetAttribute(attn_tc, cudaFuncAttributeMaxDynamicSharedMemorySize, ATTN_SMEM);
        smem_set = 1;
    }

    dim3 gQKV(DIM / 128, SEQ / 128, 3);     // (6, 32, 3)
    dim3 gD64(DIM / 64, SEQ / 128);         // (12, 32)
    dim3 gF(FFD / 128, SEQ / 128);          // (24, 32)

    ln_kernel<<<SEQ, 256>>>(hs, ln1w, ln1b, x);
    gemm_qkv<<<gQKV, 256>>>(x, wq, wk, wv, bq, bk, bv, qb_, kb_, vb_, SEQ, DIM, DIM);
    pack_kv<<<dim3(SEQ / 64, NH), 256>>>(kb_, vb_, kpk, vpk);
    attn_tc<<<dim3(SEQ / 128, NH), 256, ATTN_SMEM>>>(qb_, kpk, vpk, amask, attn);
    gemm_tc<2, 64><<<gD64, 256>>>(attn, wo, bo, hs, hidden, SEQ, DIM, DIM);
    ln_kernel<<<SEQ, 256>>>(hidden, ln2w, ln2b, y);
    gemm_tc<1, 128><<<gF, 256>>>(y, wup, bup, nullptr, ff, SEQ, FFD, DIM);
    gemm_tc<2, 64><<<gD64, 256>>>(ff, wdn, bdn, hidden, (float*)d_out, SEQ, DIM, FFD);
}

// round 6
// speedup vs baseline: 4.3766x; 2.4425x over previous
#include <cuda_runtime.h>
#include <math.h>

#define SEQ 4096
#define DIM 768
#define NH  12
#define HDD 64
#define FFD 3072

// ---------------- scratch (device globals) ----------------
__device__ float    g_x[SEQ * DIM];
__device__ unsigned g_xp[SEQ * DIM];
__device__ float    g_q[SEQ * DIM];
__device__ float    g_k[SEQ * DIM];
__device__ float    g_v[SEQ * DIM];
__device__ unsigned g_kpk[SEQ * DIM];
__device__ unsigned g_vpk[SEQ * DIM];
__device__ unsigned g_aop[SEQ * DIM];
__device__ float    g_hidden[SEQ * DIM];
__device__ float    g_y[SEQ * DIM];
__device__ unsigned g_yp[SEQ * DIM];
__device__ unsigned g_ffp[SEQ * FFD];
__device__ unsigned g_wqp[DIM * DIM];
__device__ unsigned g_wkp[DIM * DIM];
__device__ unsigned g_wvp[DIM * DIM];
__device__ unsigned g_wop[DIM * DIM];
__device__ unsigned g_wup[DIM * FFD];
__device__ unsigned g_wdp[FFD * DIM];

// ---------------- helpers ----------------
__device__ __forceinline__ void mma_tf32(float* c, const unsigned* a, const unsigned* b) {
    asm volatile(
        "mma.sync.aligned.m16n8k8.row.col.f32.tf32.tf32.f32 "
        "{%0,%1,%2,%3}, {%4,%5,%6,%7}, {%8,%9}, {%0,%1,%2,%3};"
        : "+f"(c[0]), "+f"(c[1]), "+f"(c[2]), "+f"(c[3])
        : "r"(a[0]), "r"(a[1]), "r"(a[2]), "r"(a[3]), "r"(b[0]), "r"(b[1]));
}

__device__ __forceinline__ void cpa16(void* smem, const void* gmem) {
    unsigned saddr = (unsigned)__cvta_generic_to_shared(smem);
    asm volatile("cp.async.cg.shared.global [%0], [%1], 16;" :: "r"(saddr), "l"(gmem));
}
__device__ __forceinline__ void cpa_commit() { asm volatile("cp.async.commit_group;"); }
__device__ __forceinline__ void cpa_wait0() { asm volatile("cp.async.wait_group 0;"); }
__device__ __forceinline__ void cpa_wait1() { asm volatile("cp.async.wait_group 1;"); }

__device__ __forceinline__ float block_sum_256(float v, float* red) {
    int lane = threadIdx.x & 31;
    int wid  = threadIdx.x >> 5;
    #pragma unroll
    for (int o = 16; o; o >>= 1) v += __shfl_xor_sync(0xffffffffu, v, o);
    if (lane == 0) red[wid] = v;
    __syncthreads();
    float r;
    if (wid == 0) {
        r = (lane < 8) ? red[lane] : 0.f;
        #pragma unroll
        for (int o = 4; o; o >>= 1) r += __shfl_xor_sync(0xffffffffu, r, o);
        if (lane == 0) red[0] = r;
    }
    __syncthreads();
    r = red[0];
    __syncthreads();
    return r;
}

// ---------------- LayerNorm ----------------
__global__ void __launch_bounds__(256) ln_kernel(const float* __restrict__ in,
                                                 const float* __restrict__ w,
                                                 const float* __restrict__ b,
                                                 float* __restrict__ out) {
    __shared__ float red[32];
    int row = blockIdx.x;
    const float* x = in + (size_t)row * DIM;
    int t = threadIdx.x;
    float v0 = x[t], v1 = x[t + 256], v2 = x[t + 512];
    float mu = block_sum_256(v0 + v1 + v2, red) * (1.f / DIM);
    float d0 = v0 - mu, d1 = v1 - mu, d2 = v2 - mu;
    float var = block_sum_256(d0 * d0 + d1 * d1 + d2 * d2, red) * (1.f / DIM);
    float rstd = rsqrtf(var + 1e-5f);
    float* o = out + (size_t)row * DIM;
    o[t]       = d0 * rstd * w[t]       + b[t];
    o[t + 256] = d1 * rstd * w[t + 256] + b[t + 256];
    o[t + 512] = d2 * rstd * w[t + 512] + b[t + 512];
}

// ---------------- pack A [M,K] row-major -> A-frag tiles ----------------
__global__ void __launch_bounds__(256) pack_a(const float* __restrict__ A,
                                              unsigned* __restrict__ P, int K) {
    int mb = blockIdx.x, kt = blockIdx.y, tid = threadIdx.x;
    unsigned* dst = P + ((size_t)mb * (K >> 4) + kt) * 2048;
    #pragma unroll
    for (int it = 0; it < 2; it++) {
        int fid = tid + it * 256;
        int row = fid >> 2, c4 = fid & 3;
        float4 v = *(const float4*)(A + (size_t)(mb * 128 + row) * K + kt * 16 + c4 * 4);
        int base = ((c4 >> 1) * 8 + (row >> 4)) * 128 + (row & 7) * 16
                   + ((row >> 3) & 1) + 2 * (c4 & 1);
        dst[base]      = __float_as_uint(v.x);
        dst[base + 4]  = __float_as_uint(v.y);
        dst[base + 8]  = __float_as_uint(v.z);
        dst[base + 12] = __float_as_uint(v.w);
    }
}

// ---------------- pack B [K,N] row-major -> B-frag blocks (64 cols) ----------------
__global__ void __launch_bounds__(256) pack_b(const float* __restrict__ B,
                                              unsigned* __restrict__ P, int N, int K) {
    int nb = blockIdx.x, kt = blockIdx.y, tid = threadIdx.x;
    unsigned* dst = P + ((size_t)nb * (K >> 4) + kt) * 1024;
    int kr = tid >> 4, c4 = tid & 15;
    float4 v = *(const float4*)(B + (size_t)(kt * 16 + kr) * N + nb * 64 + c4 * 4);
    int base = ((kr >> 3) * 8 + (c4 >> 1)) * 64 + (c4 & 1) * 32
               + (kr & 3) * 2 + ((kr >> 2) & 1);
    dst[base]      = __float_as_uint(v.x);
    dst[base + 8]  = __float_as_uint(v.y);
    dst[base + 16] = __float_as_uint(v.z);
    dst[base + 24] = __float_as_uint(v.w);
}

// ---------------- pack K/V into attention B-frag layout ----------------
__global__ void __launch_bounds__(256) pack_kv(const float* __restrict__ k,
                                               const float* __restrict__ v,
                                               unsigned* __restrict__ kp,
                                               unsigned* __restrict__ vp) {
    int kb = blockIdx.x, head = blockIdx.y, tid = threadIdx.x;
    int hc = head * HDD;
    size_t base = ((size_t)head * (SEQ / 64) + kb) * 4096;
    #pragma unroll
    for (int it = 0; it < 4; it++) {
        int fid = tid + it * 256;
        int row = fid >> 4, c4 = fid & 15;
        float4 kv = *(const float4*)(k + (size_t)(kb * 64 + row) * DIM + hc + c4 * 4);
        int kbse = ((c4 >> 1) * 8 + (row >> 3)) * 64 + (row & 7) * 8 + (c4 & 1);
        kp[base + kbse]     = __float_as_uint(kv.x);
        kp[base + kbse + 2] = __float_as_uint(kv.y);
        kp[base + kbse + 4] = __float_as_uint(kv.z);
        kp[base + kbse + 6] = __float_as_uint(kv.w);
        float4 vv = *(const float4*)(v + (size_t)(kb * 64 + row) * DIM + hc + c4 * 4);
        int vbse = ((row >> 3) * 8 + (c4 >> 1)) * 64 + (c4 & 1) * 32
                   + (row & 3) * 2 + ((row >> 2) & 1);
        vp[base + vbse]      = __float_as_uint(vv.x);
        vp[base + vbse + 8]  = __float_as_uint(vv.y);
        vp[base + vbse + 16] = __float_as_uint(vv.z);
        vp[base + vbse + 24] = __float_as_uint(vv.w);
    }
}

// ---------------- TF32 GEMM on pre-packed fragments, 3-stage cp.async ----------
template <int EPI, int BN, int OUTP>
__device__ __forceinline__ void gemm_core(const unsigned* __restrict__ Ap,
                                          const unsigned* __restrict__ Bp,
                                          const float* __restrict__ bias,
                                          const float* __restrict__ res,
                                          float* __restrict__ C,
                                          unsigned* __restrict__ Cp,
                                          int N, int K) {
    constexpr int NB = BN / 64;
    constexpr int MI = (BN == 128) ? 4 : 2;
    constexpr int ST = 3;
    __shared__ unsigned sA[ST][2048];
    __shared__ unsigned sB[ST][BN * 16];

    int tid = threadIdx.x, lane = tid & 31, wid = tid >> 5;
    int wm = (BN == 128) ? (wid & 1) : (wid & 3);
    int wn = (BN == 128) ? (wid >> 1) : (wid >> 2);
    int bx = blockIdx.x, by = blockIdx.y;
    int K16 = K >> 4;

    const uint4* Ab = (const uint4*)(Ap + (size_t)by * K16 * 2048);
    float acc[MI][4][4] = {};

    auto issue = [&](int kt, int st) {
        const uint4* ga = Ab + (size_t)kt * 512;
        uint4* da = (uint4*)sA[st];
        cpa16(&da[tid], &ga[tid]);
        cpa16(&da[tid + 256], &ga[tid + 256]);
        #pragma unroll
        for (int nb = 0; nb < NB; nb++) {
            const uint4* gb = (const uint4*)(Bp + ((size_t)(bx * NB + nb) * K16 + kt) * 1024);
            uint4* db = (uint4*)&sB[st][nb * 1024];
            cpa16(&db[tid], &gb[tid]);
        }
    };

    issue(0, 0); cpa_commit();
    issue(1, 1); cpa_commit();

    for (int kt = 0; kt < K16; kt++) {
        int st = kt % ST;
        cpa_wait1();
        __syncthreads();
        if (kt + 2 < K16) issue(kt + 2, (kt + 2) % ST);
        cpa_commit();
        #pragma unroll
        for (int ks = 0; ks < 2; ks++) {
            uint4 af[MI];
            uint2 bf[4];
            #pragma unroll
            for (int mi = 0; mi < MI; mi++)
                af[mi] = *(const uint4*)&sA[st][(ks * 8 + wm * MI + mi) * 128 + lane * 4];
            #pragma unroll
            for (int ni = 0; ni < 4; ni++) {
                int nf = wn * 4 + ni;
                int idx = (BN == 128)
                    ? (nf >> 3) * 1024 + (ks * 8 + (nf & 7)) * 64 + lane * 2
                    : (ks * 8 + nf) * 64 + lane * 2;
                bf[ni] = *(const uint2*)&sB[st][idx];
            }
            #pragma unroll
            for (int mi = 0; mi < MI; mi++)
                #pragma unroll
                for (int ni = 0; ni < 4; ni++)
                    mma_tf32(acc[mi][ni], &af[mi].x, &bf[ni].x);
        }
        __syncthreads();
    }

    int srcA = (lane & ~3) | ((lane & 3) >> 1);
    int srcB = srcA | 2;
    bool sel = lane & 1;

    #pragma unroll
    for (int ni = 0; ni < 4; ni++) {
        int colb = bx * BN + wn * 32 + ni * 8;
        int col = colb + (lane & 3) * 2;
        float b0 = bias[col], b1 = bias[col + 1];
        #pragma unroll
        for (int mi = 0; mi < MI; mi++) {
            int r0 = by * 128 + wm * (16 * MI) + mi * 16 + (lane >> 2);
            float v0 = acc[mi][ni][0] + b0;
            float v1 = acc[mi][ni][1] + b1;
            float v2 = acc[mi][ni][2] + b0;
            float v3 = acc[mi][ni][3] + b1;
            if (EPI == 1) {
                v0 = 0.5f * v0 * (1.f + erff(v0 * 0.70710678118654752f));
                v1 = 0.5f * v1 * (1.f + erff(v1 * 0.70710678118654752f));
                v2 = 0.5f * v2 * (1.f + erff(v2 * 0.70710678118654752f));
                v3 = 0.5f * v3 * (1.f + erff(v3 * 0.70710678118654752f));
            }
            if (EPI == 2) {
                float2 r0v = *(const float2*)&res[(size_t)r0 * N + col];
                float2 r1v = *(const float2*)&res[(size_t)(r0 + 8) * N + col];
                v0 += r0v.x; v1 += r0v.y; v2 += r1v.x; v3 += r1v.y;
            }
            if (OUTP) {
                float t0 = __shfl_sync(0xffffffffu, v0, srcA);
                float t1 = __shfl_sync(0xffffffffu, v1, srcA);
                float t2 = __shfl_sync(0xffffffffu, v2, srcA);
                float t3 = __shfl_sync(0xffffffffu, v3, srcA);
                float u0 = __shfl_sync(0xffffffffu, v0, srcB);
                float u1 = __shfl_sync(0xffffffffu, v1, srcB);
                float u2 = __shfl_sync(0xffffffffu, v2, srcB);
                float u3 = __shfl_sync(0xffffffffu, v3, srcB);
                uint4 pv;
                pv.x = __float_as_uint(sel ? t1 : t0);
                pv.y = __float_as_uint(sel ? t3 : t2);
                pv.z = __float_as_uint(sel ? u1 : u0);
                pv.w = __float_as_uint(sel ? u3 : u2);
                int ct = colb >> 4;
                *(uint4*)&Cp[((size_t)by * (N >> 4) + ct) * 2048
                             + (((ni & 1) * 8 + wm * MI + mi) * 128) + lane * 4] = pv;
            } else {
                float2 o0; o0.x = v0; o0.y = v1;
                float2 o1; o1.x = v2; o1.y = v3;
                *(float2*)&C[(size_t)r0 * N + col] = o0;
                *(float2*)&C[(size_t)(r0 + 8) * N + col] = o1;
            }
        }
    }
}

template <int EPI, int BN, int OUTP>
__global__ void __launch_bounds__(256, 2) gemm_tc(const unsigned* __restrict__ Ap,
                                                  const unsigned* __restrict__ Bp,
                                                  const float* __restrict__ bias,
                                                  const float* __restrict__ res,
                                                  float* __restrict__ C,
                                                  unsigned* __restrict__ Cp,
                                                  int N, int K) {
    gemm_core<EPI, BN, OUTP>(Ap, Bp, bias, res, C, Cp, N, K);
}

__global__ void __launch_bounds__(256, 2) gemm_qkv(const unsigned* __restrict__ Ap,
                                                   const unsigned* __restrict__ B0,
                                                   const unsigned* __restrict__ B1,
                                                   const unsigned* __restrict__ B2,
                                                   const float* __restrict__ c0,
                                                   const float* __restrict__ c1,
                                                   const float* __restrict__ c2,
                                                   float* __restrict__ O0,
                                                   float* __restrict__ O1,
                                                   float* __restrict__ O2,
                                                   int N, int K) {
    const unsigned* B = (blockIdx.z == 0) ? B0 : (blockIdx.z == 1) ? B1 : B2;
    const float* bias = (blockIdx.z == 0) ? c0 : (blockIdx.z == 1) ? c1 : c2;
    float* C = (blockIdx.z == 0) ? O0 : (blockIdx.z == 1) ? O1 : O2;
    gemm_core<0, 128, 0>(Ap, B, bias, nullptr, C, nullptr, N, K);
}

// ---------------- TF32 flash attention, packed output ----------------
__global__ void __launch_bounds__(256, 2) attn_tc(const float* __restrict__ q,
                                                  const unsigned* __restrict__ kp,
                                                  const unsigned* __restrict__ vp,
                                                  const int* __restrict__ amask,
                                                  unsigned* __restrict__ op) {
    extern __shared__ unsigned smbuf[];
    unsigned* sQ = smbuf;
    unsigned* sK = smbuf + 8192;
    unsigned* sV = smbuf + 16384;
    int* sMask = (int*)(smbuf + 24576);

    int tid = threadIdx.x, lane = tid & 31, wid = tid >> 5;
    int head = blockIdx.y;
    int qb = gridDim.x - 1 - blockIdx.x;
    int hc = head * HDD;
    int qrow0 = qb * 128;

    #pragma unroll
    for (int it = 0; it < 8; it++) {
        int fid = tid + it * 256;
        int row = fid >> 4, c4 = fid & 15;
        float4 qv = *(const float4*)(q + (size_t)(qrow0 + row) * DIM + hc + c4 * 4);
        int base = ((row >> 4) * 8 + (c4 >> 1)) * 128 + (row & 7) * 16
                   + ((row >> 3) & 1) + 2 * (c4 & 1);
        sQ[base]      = __float_as_uint(qv.x * 0.125f);
        sQ[base + 4]  = __float_as_uint(qv.y * 0.125f);
        sQ[base + 8]  = __float_as_uint(qv.z * 0.125f);
        sQ[base + 12] = __float_as_uint(qv.w * 0.125f);
    }

    int nkb = 2 * qb + 2;
    {
        size_t tb = ((size_t)head * (SEQ / 64) + 0) * 4096;
        const uint4* kg = (const uint4*)(kp + tb);
        const uint4* vg = (const uint4*)(vp + tb);
        #pragma unroll
        for (int it = 0; it < 4; it++) {
            int i = tid + it * 256;
            cpa16(&((uint4*)sK)[i], &kg[i]);
            cpa16(&((uint4*)sV)[i], &vg[i]);
        }
        cpa_commit();
        if (tid < 64) sMask[tid] = amask[tid];
    }

    float m0 = -1e30f, m1 = -1e30f, l0 = 0.f, l1 = 0.f;
    float oacc[8][4] = {};
    int r0g = qrow0 + wid * 16 + (lane >> 2);

    int srcA = (lane & ~3) | ((lane & 3) >> 1);
    int srcB = srcA | 2;
    bool sel = lane & 1;

    for (int kb = 0; kb < nkb; kb++) {
        int cur = kb & 1;
        cpa_wait0();
        __syncthreads();

        if (kb + 1 < nkb) {
            size_t tb = ((size_t)head * (SEQ / 64) + (kb + 1)) * 4096;
            const uint4* kg = (const uint4*)(kp + tb);
            const uint4* vg = (const uint4*)(vp + tb);
            uint4* dk = (uint4*)(sK + (cur ^ 1) * 4096);
            uint4* dv = (uint4*)(sV + (cur ^ 1) * 4096);
            #pragma unroll
            for (int it = 0; it < 4; it++) {
                int i = tid + it * 256;
                cpa16(&dk[i], &kg[i]);
                cpa16(&dv[i], &vg[i]);
            }
            cpa_commit();
            if (tid < 64) sMask[(cur ^ 1) * 64 + tid] = amask[(kb + 1) * 64 + tid];
        }

        const unsigned* cK = sK + cur * 4096;
        const unsigned* cV = sV + cur * 4096;
        const int* cM = sMask + cur * 64;

        float s[8][4] = {};
        #pragma unroll
        for (int ks = 0; ks < 8; ks++) {
            uint4 a = *(const uint4*)&sQ[(wid * 8 + ks) * 128 + lane * 4];
            #pragma unroll
            for (int nf = 0; nf < 8; nf++) {
                uint2 b = *(const uint2*)&cK[(ks * 8 + nf) * 64 + lane * 2];
                mma_tf32(s[nf], &a.x, &b.x);
            }
        }

        #pragma unroll
        for (int nf = 0; nf < 8; nf++) {
            int cl = nf * 8 + (lane & 3) * 2;
            int c0 = kb * 64 + cl;
            bool p0 = (cM[cl] == 0), p1 = (cM[cl + 1] == 0);
            if ((c0 > r0g) || p0)           s[nf][0] = -1e30f;
            if ((c0 + 1 > r0g) || p1)       s[nf][1] = -1e30f;
            if ((c0 > r0g + 8) || p0)       s[nf][2] = -1e30f;
            if ((c0 + 1 > r0g + 8) || p1)   s[nf][3] = -1e30f;
        }

        float mx0 = -1e30f, mx1 = -1e30f;
        #pragma unroll
        for (int nf = 0; nf < 8; nf++) {
            mx0 = fmaxf(mx0, fmaxf(s[nf][0], s[nf][1]));
            mx1 = fmaxf(mx1, fmaxf(s[nf][2], s[nf][3]));
        }
        mx0 = fmaxf(mx0, __shfl_xor_sync(0xffffffffu, mx0, 1));
        mx0 = fmaxf(mx0, __shfl_xor_sync(0xffffffffu, mx0, 2));
        mx1 = fmaxf(mx1, __shfl_xor_sync(0xffffffffu, mx1, 1));
        mx1 = fmaxf(mx1, __shfl_xor_sync(0xffffffffu, mx1, 2));
        float mn0 = fmaxf(m0, mx0), mn1 = fmaxf(m1, mx1);
        float f0 = __expf(m0 - mn0), f1 = __expf(m1 - mn1);
        float sum0 = 0.f, sum1 = 0.f;
        #pragma unroll
        for (int nf = 0; nf < 8; nf++) {
            s[nf][0] = __expf(s[nf][0] - mn0);
            s[nf][1] = __expf(s[nf][1] - mn0);
            s[nf][2] = __expf(s[nf][2] - mn1);
            s[nf][3] = __expf(s[nf][3] - mn1);
            sum0 += s[nf][0] + s[nf][1];
            sum1 += s[nf][2] + s[nf][3];
        }
        sum0 += __shfl_xor_sync(0xffffffffu, sum0, 1);
        sum0 += __shfl_xor_sync(0xffffffffu, sum0, 2);
        sum1 += __shfl_xor_sync(0xffffffffu, sum1, 1);
        sum1 += __shfl_xor_sync(0xffffffffu, sum1, 2);
        l0 = l0 * f0 + sum0;
        l1 = l1 * f1 + sum1;
        m0 = mn0; m1 = mn1;
        #pragma unroll
        for (int nf = 0; nf < 8; nf++) {
            oacc[nf][0] *= f0; oacc[nf][1] *= f0;
            oacc[nf][2] *= f1; oacc[nf][3] *= f1;
        }

        #pragma unroll
        for (int ks = 0; ks < 8; ks++) {
            float t0 = __shfl_sync(0xffffffffu, s[ks][0], srcA);
            float t1 = __shfl_sync(0xffffffffu, s[ks][1], srcA);
            float t2 = __shfl_sync(0xffffffffu, s[ks][2], srcA);
            float t3 = __shfl_sync(0xffffffffu, s[ks][3], srcA);
            float u0 = __shfl_sync(0xffffffffu, s[ks][0], srcB);
            float u1 = __shfl_sync(0xffffffffu, s[ks][1], srcB);
            float u2 = __shfl_sync(0xffffffffu, s[ks][2], srcB);
            float u3 = __shfl_sync(0xffffffffu, s[ks][3], srcB);
            unsigned a[4];
            a[0] = __float_as_uint(sel ? t1 : t0);
            a[1] = __float_as_uint(sel ? t3 : t2);
            a[2] = __float_as_uint(sel ? u1 : u0);
            a[3] = __float_as_uint(sel ? u3 : u2);
            #pragma unroll
            for (int nf = 0; nf < 8; nf++) {
                uint2 b = *(const uint2*)&cV[(ks * 8 + nf) * 64 + lane * 2];
                mma_tf32(oacc[nf], a, &b.x);
            }
        }
    }

    float inv0 = 1.f / l0, inv1 = 1.f / l1;
    int mb = qrow0 >> 7;
    #pragma unroll
    for (int nf = 0; nf < 8; nf++) {
        float v0 = oacc[nf][0] * inv0;
        float v1 = oacc[nf][1] * inv0;
        float v2 = oacc[nf][2] * inv1;
        float v3 = oacc[nf][3] * inv1;
        float t0 = __shfl_sync(0xffffffffu, v0, srcA);
        float t1 = __shfl_sync(0xffffffffu, v1, srcA);
        float t2 = __shfl_sync(0xffffffffu, v2, srcA);
        float t3 = __shfl_sync(0xffffffffu, v3, srcA);
        float u0 = __shfl_sync(0xffffffffu, v0, srcB);
        float u1 = __shfl_sync(0xffffffffu, v1, srcB);
        float u2 = __shfl_sync(0xffffffffu, v2, srcB);
        float u3 = __shfl_sync(0xffffffffu, v3, srcB);
        uint4 pv;
        pv.x = __float_as_uint(sel ? t1 : t0);
        pv.y = __float_as_uint(sel ? t3 : t2);
        pv.z = __float_as_uint(sel ? u1 : u0);
        pv.w = __float_as_uint(sel ? u3 : u2);
        int ct = (hc + nf * 8) >> 4;
        *(uint4*)&op[((size_t)mb * (DIM / 16) + ct) * 2048
                     + (((nf & 1) * 8 + wid) * 128) + lane * 4] = pv;
    }
}

#define ATTN_SMEM ((24576 + 128) * 4)

// ---------------- launch ----------------
extern "C" void kernel_launch(void* const* d_in, const int* in_sizes, int n_in,
                              void* d_out, int out_size) {
    const float* hs    = (const float*)d_in[0];
    const int*   amask = (const int*)d_in[1];
    const float* ln1w  = (const float*)d_in[2];
    const float* ln1b  = (const float*)d_in[3];
    const float* wq    = (const float*)d_in[4];
    const float* bq    = (const float*)d_in[5];
    const float* wk    = (const float*)d_in[6];
    const float* bk    = (const float*)d_in[7];
    const float* wv    = (const float*)d_in[8];
    const float* bv    = (const float*)d_in[9];
    const float* wo    = (const float*)d_in[10];
    const float* bo    = (const float*)d_in[11];
    const float* ln2w  = (const float*)d_in[12];
    const float* ln2b  = (const float*)d_in[13];
    const float* wup   = (const float*)d_in[14];
    const float* bup   = (const float*)d_in[15];
    const float* wdn   = (const float*)d_in[16];
    const float* bdn   = (const float*)d_in[17];

    float *x, *qb_, *kb_, *vb_, *hidden, *y;
    unsigned *xp, *kpk, *vpk, *aop, *yp, *ffp;
    unsigned *wqp, *wkp, *wvp, *wop, *wupp, *wdp;
    cudaGetSymbolAddress((void**)&x, g_x);
    cudaGetSymbolAddress((void**)&xp, g_xp);
    cudaGetSymbolAddress((void**)&qb_, g_q);
    cudaGetSymbolAddress((void**)&kb_, g_k);
    cudaGetSymbolAddress((void**)&vb_, g_v);
    cudaGetSymbolAddress((void**)&kpk, g_kpk);
    cudaGetSymbolAddress((void**)&vpk, g_vpk);
    cudaGetSymbolAddress((void**)&aop, g_aop);
    cudaGetSymbolAddress((void**)&hidden, g_hidden);
    cudaGetSymbolAddress((void**)&y, g_y);
    cudaGetSymbolAddress((void**)&yp, g_yp);
    cudaGetSymbolAddress((void**)&ffp, g_ffp);
    cudaGetSymbolAddress((void**)&wqp, g_wqp);
    cudaGetSymbolAddress((void**)&wkp, g_wkp);
    cudaGetSymbolAddress((void**)&wvp, g_wvp);
    cudaGetSymbolAddress((void**)&wop, g_wop);
    cudaGetSymbolAddress((void**)&wupp, g_wup);
    cudaGetSymbolAddress((void**)&wdp, g_wdp);

    static int smem_set = 0;
    if (!smem_set) {
        cudaFuncSetAttribute(attn_tc, cudaFuncAttributeMaxDynamicSharedMemorySize, ATTN_SMEM);
        smem_set = 1;
    }

    // one-time-per-launch weight packs (memory-bound, ~26 MB total)
    pack_b<<<dim3(DIM / 64, DIM / 16), 256>>>(wq, wqp, DIM, DIM);
    pack_b<<<dim3(DIM / 64, DIM / 16), 256>>>(wk, wkp, DIM, DIM);
    pack_b<<<dim3(DIM / 64, DIM / 16), 256>>>(wv, wvp, DIM, DIM);
    pack_b<<<dim3(DIM / 64, DIM / 16), 256>>>(wo, wop, DIM, DIM);
    pack_b<<<dim3(FFD / 64, DIM / 16), 256>>>(wup, wupp, FFD, DIM);
    pack_b<<<dim3(DIM / 64, FFD / 16), 256>>>(wdn, wdp, DIM, FFD);

    ln_kernel<<<SEQ, 256>>>(hs, ln1w, ln1b, x);
    pack_a<<<dim3(SEQ / 128, DIM / 16), 256>>>(x, xp, DIM);
    gemm_qkv<<<dim3(DIM / 128, SEQ / 128, 3), 256>>>(xp, wqp, wkp, wvp, bq, bk, bv,
                                                     qb_, kb_, vb_, DIM, DIM);
    pack_kv<<<dim3(SEQ / 64, NH), 256>>>(kb_, vb_, kpk, vpk);
    attn_tc<<<dim3(SEQ / 128, NH), 256, ATTN_SMEM>>>(qb_, kpk, vpk, amask, aop);
    gemm_tc<2, 64, 0><<<dim3(DIM / 64, SEQ / 128), 256>>>(aop, wop, bo, hs,
                                                          hidden, nullptr, DIM, DIM);
    ln_kernel<<<SEQ, 256>>>(hidden, ln2w, ln2b, y);
    pack_a<<<dim3(SEQ / 128, DIM / 16), 256>>>(y, yp, DIM);
    gemm_tc<1, 128, 1><<<dim3(FFD / 128, SEQ / 128), 256>>>(yp, wupp, bup, nullptr,
                                                            nullptr, ffp, FFD, DIM);
    gemm_tc<2, 64, 0><<<dim3(DIM / 64, SEQ / 128), 256>>>(ffp, wdp, bdn, hidden,
                                                          (float*)d_out, nullptr, DIM, FFD);
}

// round 7
// speedup vs baseline: 4.6342x; 1.0589x over previous
#include <cuda_runtime.h>
#include <math.h>

#define SEQ 4096
#define DIM 768
#define NH  12
#define HDD 64
#define FFD 3072

// ---------------- scratch (device globals) ----------------
__device__ unsigned g_xp[SEQ * DIM];    // ln1 out, packed A-frags
__device__ unsigned g_qp[SEQ * DIM];    // Q (scaled), packed A-frags
__device__ unsigned g_kpk[SEQ * DIM];   // K, attention B-frag tiles
__device__ unsigned g_vpk[SEQ * DIM];   // V, attention B-frag tiles
__device__ unsigned g_aop[SEQ * DIM];   // attention out, packed A-frags
__device__ float    g_hidden[SEQ * DIM];
__device__ unsigned g_yp[SEQ * DIM];    // ln2 out, packed A-frags
__device__ unsigned g_ffp[SEQ * FFD];   // gelu(up), packed A-frags
__device__ unsigned g_wqp[DIM * DIM];
__device__ unsigned g_wkp[DIM * DIM];
__device__ unsigned g_wvp[DIM * DIM];
__device__ unsigned g_wop[DIM * DIM];
__device__ unsigned g_wup[DIM * FFD];
__device__ unsigned g_wdp[FFD * DIM];

// ---------------- helpers ----------------
__device__ __forceinline__ void mma_tf32(float* c, const unsigned* a, const unsigned* b) {
    asm volatile(
        "mma.sync.aligned.m16n8k8.row.col.f32.tf32.tf32.f32 "
        "{%0,%1,%2,%3}, {%4,%5,%6,%7}, {%8,%9}, {%0,%1,%2,%3};"
        : "+f"(c[0]), "+f"(c[1]), "+f"(c[2]), "+f"(c[3])
        : "r"(a[0]), "r"(a[1]), "r"(a[2]), "r"(a[3]), "r"(b[0]), "r"(b[1]));
}

__device__ __forceinline__ void cpa16(void* smem, const void* gmem) {
    unsigned saddr = (unsigned)__cvta_generic_to_shared(smem);
    asm volatile("cp.async.cg.shared.global [%0], [%1], 16;" :: "r"(saddr), "l"(gmem));
}
__device__ __forceinline__ void cpa_commit() { asm volatile("cp.async.commit_group;"); }
__device__ __forceinline__ void cpa_wait0() { asm volatile("cp.async.wait_group 0;"); }
__device__ __forceinline__ void cpa_wait1() { asm volatile("cp.async.wait_group 1;"); }

__device__ __forceinline__ float block_sum_256(float v, float* red) {
    int lane = threadIdx.x & 31;
    int wid  = threadIdx.x >> 5;
    #pragma unroll
    for (int o = 16; o; o >>= 1) v += __shfl_xor_sync(0xffffffffu, v, o);
    if (lane == 0) red[wid] = v;
    __syncthreads();
    float r;
    if (wid == 0) {
        r = (lane < 8) ? red[lane] : 0.f;
        #pragma unroll
        for (int o = 4; o; o >>= 1) r += __shfl_xor_sync(0xffffffffu, r, o);
        if (lane == 0) red[0] = r;
    }
    __syncthreads();
    r = red[0];
    __syncthreads();
    return r;
}

// ---------------- LayerNorm fused with A-frag packing ----------------
__global__ void __launch_bounds__(256) ln_pack(const float* __restrict__ in,
                                               const float* __restrict__ w,
                                               const float* __restrict__ b,
                                               unsigned* __restrict__ P) {
    __shared__ float red[32];
    int row = blockIdx.x;
    const float* x = in + (size_t)row * DIM;
    int t = threadIdx.x;
    float v0 = x[t], v1 = x[t + 256], v2 = x[t + 512];
    float mu = block_sum_256(v0 + v1 + v2, red) * (1.f / DIM);
    float d0 = v0 - mu, d1 = v1 - mu, d2 = v2 - mu;
    float var = block_sum_256(d0 * d0 + d1 * d1 + d2 * d2, red) * (1.f / DIM);
    float rstd = rsqrtf(var + 1e-5f);
    int mb = row >> 7, rl = row & 127;
    int rbase = (rl >> 4) * 128 + (rl & 7) * 16 + ((rl >> 3) & 1);
    #pragma unroll
    for (int p = 0; p < 3; p++) {
        int col = t + p * 256;
        float d = (p == 0) ? d0 : (p == 1) ? d1 : d2;
        float val = d * rstd * w[col] + b[col];
        int kt = col >> 4, cc = col & 15, c4 = cc >> 2, j = cc & 3;
        P[((size_t)mb * 48 + kt) * 2048 + (c4 >> 1) * 1024 + rbase
          + 2 * (c4 & 1) + 4 * j] = __float_as_uint(val);
    }
}

// ---------------- pack B [K,N] row-major -> B-frag blocks (64 cols) ----------------
__global__ void __launch_bounds__(256) pack_b(const float* __restrict__ B,
                                              unsigned* __restrict__ P, int N, int K) {
    int nb = blockIdx.x, kt = blockIdx.y, tid = threadIdx.x;
    unsigned* dst = P + ((size_t)nb * (K >> 4) + kt) * 1024;
    int kr = tid >> 4, c4 = tid & 15;
    float4 v = *(const float4*)(B + (size_t)(kt * 16 + kr) * N + nb * 64 + c4 * 4);
    int base = ((kr >> 3) * 8 + (c4 >> 1)) * 64 + (c4 & 1) * 32
               + (kr & 3) * 2 + ((kr >> 2) & 1);
    dst[base]      = __float_as_uint(v.x);
    dst[base + 8]  = __float_as_uint(v.y);
    dst[base + 16] = __float_as_uint(v.z);
    dst[base + 24] = __float_as_uint(v.w);
}

// ---------------- TF32 GEMM, packed operands, 32-K stages, 1 sync/stage ----------
// OUTP: 0 row-major C, 1 packed A-frag Cp, 2 attention-K B-frag Cp, 3 attention-V B-frag Cp
template <int EPI, int BN, int OUTP>
__device__ __forceinline__ void gemm_core(const unsigned* __restrict__ Ap,
                                          const unsigned* __restrict__ Bp,
                                          const float* __restrict__ bias,
                                          const float* __restrict__ res,
                                          float* __restrict__ C,
                                          unsigned* __restrict__ Cp,
                                          int N, int K, float scale) {
    constexpr int NB = BN / 64;
    constexpr int MI = (BN == 128) ? 4 : 2;
    constexpr int ST = 3;
    constexpr int BN32 = BN * 32;
    extern __shared__ unsigned smem_u[];
    unsigned* sA = smem_u;                 // ST * 4096
    unsigned* sB = smem_u + ST * 4096;     // ST * BN32

    int tid = threadIdx.x, lane = tid & 31, wid = tid >> 5;
    int wm = (BN == 128) ? (wid & 1) : (wid & 3);
    int wn = (BN == 128) ? (wid >> 1) : (wid >> 2);
    int bx = blockIdx.x, by = blockIdx.y;
    int K16 = K >> 4, nt32 = K >> 5;

    const uint4* Ab = (const uint4*)(Ap + (size_t)by * K16 * 2048);
    float acc[MI][4][4] = {};

    auto issue = [&](int kt32, int st) {
        const uint4* ga = Ab + (size_t)kt32 * 1024;
        uint4* da = (uint4*)&sA[st * 4096];
        #pragma unroll
        for (int i = 0; i < 4; i++) cpa16(&da[tid + i * 256], &ga[tid + i * 256]);
        #pragma unroll
        for (int nb = 0; nb < NB; nb++) {
            const uint4* gb = (const uint4*)(Bp + ((size_t)(bx * NB + nb) * K16 + kt32 * 2) * 1024);
            uint4* db = (uint4*)&sB[st * BN32 + nb * 2048];
            cpa16(&db[tid], &gb[tid]);
            cpa16(&db[tid + 256], &gb[tid + 256]);
        }
    };

    issue(0, 0); cpa_commit();
    issue(1, 1); cpa_commit();

    for (int kt = 0; kt < nt32; kt++) {
        int st = kt % ST;
        cpa_wait1();
        __syncthreads();
        if (kt + 2 < nt32) issue(kt + 2, (kt + 2) % ST);
        cpa_commit();
        #pragma unroll
        for (int half = 0; half < 2; half++) {
            #pragma unroll
            for (int ks = 0; ks < 2; ks++) {
                uint4 af[MI];
                uint2 bf[4];
                #pragma unroll
                for (int mi = 0; mi < MI; mi++)
                    af[mi] = *(const uint4*)&sA[st * 4096 + half * 2048
                                                + (ks * 8 + wm * MI + mi) * 128 + lane * 4];
                #pragma unroll
                for (int ni = 0; ni < 4; ni++) {
                    int nf = wn * 4 + ni;
                    int idx = st * BN32 + ((BN == 128) ? (nf >> 3) * 2048 : 0) + half * 1024
                              + (ks * 8 + ((BN == 128) ? (nf & 7) : nf)) * 64 + lane * 2;
                    bf[ni] = *(const uint2*)&sB[idx];
                }
                #pragma unroll
                for (int mi = 0; mi < MI; mi++)
                    #pragma unroll
                    for (int ni = 0; ni < 4; ni++)
                        mma_tf32(acc[mi][ni], &af[mi].x, &bf[ni].x);
            }
        }
    }
    __syncthreads();

    int srcA = (lane & ~3) | ((lane & 3) >> 1);
    int srcB = srcA | 2;
    bool sel = lane & 1;
    int srcV0 = (lane & 3) * 4 + (lane >> 3);
    int srcV1 = srcV0 + 16;
    bool selV = (lane >> 2) & 1;

    #pragma unroll
    for (int ni = 0; ni < 4; ni++) {
        int colb = bx * BN + wn * 32 + ni * 8;
        int col = colb + (lane & 3) * 2;
        float b0 = bias[col], b1 = bias[col + 1];
        #pragma unroll
        for (int mi = 0; mi < MI; mi++) {
            int r0b = by * 128 + wm * (16 * MI) + mi * 16;
            int r0 = r0b + (lane >> 2);
            float v0 = acc[mi][ni][0] + b0;
            float v1 = acc[mi][ni][1] + b1;
            float v2 = acc[mi][ni][2] + b0;
            float v3 = acc[mi][ni][3] + b1;
            if (EPI == 1) {
                v0 = 0.5f * v0 * (1.f + erff(v0 * 0.70710678118654752f));
                v1 = 0.5f * v1 * (1.f + erff(v1 * 0.70710678118654752f));
                v2 = 0.5f * v2 * (1.f + erff(v2 * 0.70710678118654752f));
                v3 = 0.5f * v3 * (1.f + erff(v3 * 0.70710678118654752f));
            }
            if (EPI == 2) {
                float2 r0v = *(const float2*)&res[(size_t)r0 * N + col];
                float2 r1v = *(const float2*)&res[(size_t)(r0 + 8) * N + col];
                v0 += r0v.x; v1 += r0v.y; v2 += r1v.x; v3 += r1v.y;
            }
            if (OUTP == 0) {
                float2 o0; o0.x = v0; o0.y = v1;
                float2 o1; o1.x = v2; o1.y = v3;
                *(float2*)&C[(size_t)r0 * N + col] = o0;
                *(float2*)&C[(size_t)(r0 + 8) * N + col] = o1;
            } else if (OUTP == 1) {
                v0 *= scale; v1 *= scale; v2 *= scale; v3 *= scale;
                float t0 = __shfl_sync(0xffffffffu, v0, srcA);
                float t1 = __shfl_sync(0xffffffffu, v1, srcA);
                float t2 = __shfl_sync(0xffffffffu, v2, srcA);
                float t3 = __shfl_sync(0xffffffffu, v3, srcA);
                float u0 = __shfl_sync(0xffffffffu, v0, srcB);
                float u1 = __shfl_sync(0xffffffffu, v1, srcB);
                float u2 = __shfl_sync(0xffffffffu, v2, srcB);
                float u3 = __shfl_sync(0xffffffffu, v3, srcB);
                uint4 pv;
                pv.x = __float_as_uint(sel ? t1 : t0);
                pv.y = __float_as_uint(sel ? t3 : t2);
                pv.z = __float_as_uint(sel ? u1 : u0);
                pv.w = __float_as_uint(sel ? u3 : u2);
                int ct = colb >> 4;
                *(uint4*)&Cp[((size_t)by * (N >> 4) + ct) * 2048
                             + (((ni & 1) * 8 + wm * MI + mi) * 128) + lane * 4] = pv;
            } else if (OUTP == 2) {
                // attention K B-frag: same shuffle as A-frag, regrouped stores
                float t0 = __shfl_sync(0xffffffffu, v0, srcA);
                float t1 = __shfl_sync(0xffffffffu, v1, srcA);
                float t2 = __shfl_sync(0xffffffffu, v2, srcA);
                float t3 = __shfl_sync(0xffffffffu, v3, srcA);
                float u0 = __shfl_sync(0xffffffffu, v0, srcB);
                float u1 = __shfl_sync(0xffffffffu, v1, srcB);
                float u2 = __shfl_sync(0xffffffffu, v2, srcB);
                float u3 = __shfl_sync(0xffffffffu, v3, srcB);
                int head = colb >> 6, ksd = (colb & 63) >> 3;
                int kb = r0b >> 6, nf = (r0b >> 3) & 7;
                size_t tb = ((size_t)head * (SEQ / 64) + kb) * 4096;
                uint2 lo, hi;
                lo.x = __float_as_uint(sel ? t1 : t0);
                lo.y = __float_as_uint(sel ? u1 : u0);
                hi.x = __float_as_uint(sel ? t3 : t2);
                hi.y = __float_as_uint(sel ? u3 : u2);
                *(uint2*)&Cp[tb + (ksd * 8 + nf) * 64 + lane * 2] = lo;
                *(uint2*)&Cp[tb + (ksd * 8 + nf + 1) * 64 + lane * 2] = hi;
            } else {
                // attention V B-frag: transpose shuffle
                float w0 = __shfl_sync(0xffffffffu, v0, srcV0);
                float w1 = __shfl_sync(0xffffffffu, v1, srcV0);
                float x0 = __shfl_sync(0xffffffffu, v0, srcV1);
                float x1 = __shfl_sync(0xffffffffu, v1, srcV1);
                float y0 = __shfl_sync(0xffffffffu, v2, srcV0);
                float y1 = __shfl_sync(0xffffffffu, v3, srcV0);
                float z0 = __shfl_sync(0xffffffffu, v2, srcV1);
                float z1 = __shfl_sync(0xffffffffu, v3, srcV1);
                int head = colb >> 6, nfd = (colb & 63) >> 3;
                int kb = r0b >> 6, ksv = (r0b >> 3) & 7;
                size_t tb = ((size_t)head * (SEQ / 64) + kb) * 4096;
                uint2 lo, hi;
                lo.x = __float_as_uint(selV ? w1 : w0);
                lo.y = __float_as_uint(selV ? x1 : x0);
                hi.x = __float_as_uint(selV ? y1 : y0);
                hi.y = __float_as_uint(selV ? z1 : z0);
                *(uint2*)&Cp[tb + (ksv * 8 + nfd) * 64 + lane * 2] = lo;
                *(uint2*)&Cp[tb + ((ksv + 1) * 8 + nfd) * 64 + lane * 2] = hi;
            }
        }
    }
}

template <int EPI, int BN, int OUTP>
__global__ void __launch_bounds__(256, 2) gemm_tc(const unsigned* __restrict__ Ap,
                                                  const unsigned* __restrict__ Bp,
                                                  const float* __restrict__ bias,
                                                  const float* __restrict__ res,
                                                  float* __restrict__ C,
                                                  unsigned* __restrict__ Cp,
                                                  int N, int K, float scale) {
    gemm_core<EPI, BN, OUTP>(Ap, Bp, bias, res, C, Cp, N, K, scale);
}

__global__ void __launch_bounds__(256, 2) gemm_qkv(const unsigned* __restrict__ Ap,
                                                   const unsigned* __restrict__ B0,
                                                   const unsigned* __restrict__ B1,
                                                   const unsigned* __restrict__ B2,
                                                   const float* __restrict__ c0,
                                                   const float* __restrict__ c1,
                                                   const float* __restrict__ c2,
                                                   unsigned* __restrict__ Qp,
                                                   unsigned* __restrict__ Kp,
                                                   unsigned* __restrict__ Vp) {
    if (blockIdx.z == 0)
        gemm_core<0, 128, 1>(Ap, B0, c0, nullptr, nullptr, Qp, DIM, DIM, 0.125f);
    else if (blockIdx.z == 1)
        gemm_core<0, 128, 2>(Ap, B1, c1, nullptr, nullptr, Kp, DIM, DIM, 1.f);
    else
        gemm_core<0, 128, 3>(Ap, B2, c2, nullptr, nullptr, Vp, DIM, DIM, 1.f);
}

// ---------------- TF32 flash attention, fully packed I/O ----------------
__global__ void __launch_bounds__(256, 2) attn_tc(const unsigned* __restrict__ qp,
                                                  const unsigned* __restrict__ kp,
                                                  const unsigned* __restrict__ vp,
                                                  const int* __restrict__ amask,
                                                  unsigned* __restrict__ op) {
    extern __shared__ unsigned smbuf[];
    unsigned* sQ = smbuf;                 // 8192
    unsigned* sK = smbuf + 8192;          // 2 x 4096
    unsigned* sV = smbuf + 16384;         // 2 x 4096
    int* sMask = (int*)(smbuf + 24576);   // 2 x 64

    int tid = threadIdx.x, lane = tid & 31, wid = tid >> 5;
    int head = blockIdx.y;
    int qb = gridDim.x - 1 - blockIdx.x;
    int hc = head * HDD;
    int qrow0 = qb * 128;

    int nkb = 2 * qb + 2;
    // prologue: cp.async Q (packed tiles) + K/V tile 0 + mask
    {
        const uint4* qg = (const uint4*)(qp + ((size_t)qb * 48 + head * 4) * 2048);
        uint4* dq = (uint4*)sQ;
        #pragma unroll
        for (int it = 0; it < 8; it++) cpa16(&dq[tid + it * 256], &qg[tid + it * 256]);
        size_t tb = ((size_t)head * (SEQ / 64)) * 4096;
        const uint4* kg = (const uint4*)(kp + tb);
        const uint4* vg = (const uint4*)(vp + tb);
        #pragma unroll
        for (int it = 0; it < 4; it++) {
            int i = tid + it * 256;
            cpa16(&((uint4*)sK)[i], &kg[i]);
            cpa16(&((uint4*)sV)[i], &vg[i]);
        }
        cpa_commit();
        if (tid < 64) sMask[tid] = amask[tid];
    }

    float m0 = -1e30f, m1 = -1e30f, l0 = 0.f, l1 = 0.f;
    float oacc[8][4] = {};
    int r0g = qrow0 + wid * 16 + (lane >> 2);

    int srcA = (lane & ~3) | ((lane & 3) >> 1);
    int srcB = srcA | 2;
    bool sel = lane & 1;

    for (int kb = 0; kb < nkb; kb++) {
        int cur = kb & 1;
        cpa_wait0();
        __syncthreads();

        if (kb + 1 < nkb) {
            size_t tb = ((size_t)head * (SEQ / 64) + (kb + 1)) * 4096;
            const uint4* kg = (const uint4*)(kp + tb);
            const uint4* vg = (const uint4*)(vp + tb);
            uint4* dk = (uint4*)(sK + (cur ^ 1) * 4096);
            uint4* dv = (uint4*)(sV + (cur ^ 1) * 4096);
            #pragma unroll
            for (int it = 0; it < 4; it++) {
                int i = tid + it * 256;
                cpa16(&dk[i], &kg[i]);
                cpa16(&dv[i], &vg[i]);
            }
            cpa_commit();
            if (tid < 64) sMask[(cur ^ 1) * 64 + tid] = amask[(kb + 1) * 64 + tid];
        }

        const unsigned* cK = sK + cur * 4096;
        const unsigned* cV = sV + cur * 4096;
        const int* cM = sMask + cur * 64;

        float s[8][4] = {};
        #pragma unroll
        for (int ks = 0; ks < 8; ks++) {
            uint4 a = *(const uint4*)&sQ[(ks >> 1) * 2048 + (ks & 1) * 1024
                                          + wid * 128 + lane * 4];
            #pragma unroll
            for (int nf = 0; nf < 8; nf++) {
                uint2 b = *(const uint2*)&cK[(ks * 8 + nf) * 64 + lane * 2];
                mma_tf32(s[nf], &a.x, &b.x);
            }
        }

        #pragma unroll
        for (int nf = 0; nf < 8; nf++) {
            int cl = nf * 8 + (lane & 3) * 2;
            int c0 = kb * 64 + cl;
            bool p0 = (cM[cl] == 0), p1 = (cM[cl + 1] == 0);
            if ((c0 > r0g) || p0)           s[nf][0] = -1e30f;
            if ((c0 + 1 > r0g) || p1)       s[nf][1] = -1e30f;
            if ((c0 > r0g + 8) || p0)       s[nf][2] = -1e30f;
            if ((c0 + 1 > r0g + 8) || p1)   s[nf][3] = -1e30f;
        }

        float mx0 = -1e30f, mx1 = -1e30f;
        #pragma unroll
        for (int nf = 0; nf < 8; nf++) {
            mx0 = fmaxf(mx0, fmaxf(s[nf][0], s[nf][1]));
            mx1 = fmaxf(mx1, fmaxf(s[nf][2], s[nf][3]));
        }
        mx0 = fmaxf(mx0, __shfl_xor_sync(0xffffffffu, mx0, 1));
        mx0 = fmaxf(mx0, __shfl_xor_sync(0xffffffffu, mx0, 2));
        mx1 = fmaxf(mx1, __shfl_xor_sync(0xffffffffu, mx1, 1));
        mx1 = fmaxf(mx1, __shfl_xor_sync(0xffffffffu, mx1, 2));
        float mn0 = fmaxf(m0, mx0), mn1 = fmaxf(m1, mx1);
        float f0 = __expf(m0 - mn0), f1 = __expf(m1 - mn1);
        float sum0 = 0.f, sum1 = 0.f;
        #pragma unroll
        for (int nf = 0; nf < 8; nf++) {
            s[nf][0] = __expf(s[nf][0] - mn0);
            s[nf][1] = __expf(s[nf][1] - mn0);
            s[nf][2] = __expf(s[nf][2] - mn1);
            s[nf][3] = __expf(s[nf][3] - mn1);
            sum0 += s[nf][0] + s[nf][1];
            sum1 += s[nf][2] + s[nf][3];
        }
        sum0 += __shfl_xor_sync(0xffffffffu, sum0, 1);
        sum0 += __shfl_xor_sync(0xffffffffu, sum0, 2);
        sum1 += __shfl_xor_sync(0xffffffffu, sum1, 1);
        sum1 += __shfl_xor_sync(0xffffffffu, sum1, 2);
        l0 = l0 * f0 + sum0;
        l1 = l1 * f1 + sum1;
        m0 = mn0; m1 = mn1;
        #pragma unroll
        for (int nf = 0; nf < 8; nf++) {
            oacc[nf][0] *= f0; oacc[nf][1] *= f0;
            oacc[nf][2] *= f1; oacc[nf][3] *= f1;
        }

        #pragma unroll
        for (int ks = 0; ks < 8; ks++) {
            float t0 = __shfl_sync(0xffffffffu, s[ks][0], srcA);
            float t1 = __shfl_sync(0xffffffffu, s[ks][1], srcA);
            float t2 = __shfl_sync(0xffffffffu, s[ks][2], srcA);
            float t3 = __shfl_sync(0xffffffffu, s[ks][3], srcA);
            float u0 = __shfl_sync(0xffffffffu, s[ks][0], srcB);
            float u1 = __shfl_sync(0xffffffffu, s[ks][1], srcB);
            float u2 = __shfl_sync(0xffffffffu, s[ks][2], srcB);
            float u3 = __shfl_sync(0xffffffffu, s[ks][3], srcB);
            unsigned a[4];
            a[0] = __float_as_uint(sel ? t1 : t0);
            a[1] = __float_as_uint(sel ? t3 : t2);
            a[2] = __float_as_uint(sel ? u1 : u0);
            a[3] = __float_as_uint(sel ? u3 : u2);
            #pragma unroll
            for (int nf = 0; nf < 8; nf++) {
                uint2 b = *(const uint2*)&cV[(ks * 8 + nf) * 64 + lane * 2];
                mma_tf32(oacc[nf], a, &b.x);
            }
        }
    }

    float inv0 = 1.f / l0, inv1 = 1.f / l1;
    #pragma unroll
    for (int nf = 0; nf < 8; nf++) {
        float v0 = oacc[nf][0] * inv0;
        float v1 = oacc[nf][1] * inv0;
        float v2 = oacc[nf][2] * inv1;
        float v3 = oacc[nf][3] * inv1;
        float t0 = __shfl_sync(0xffffffffu, v0, srcA);
        float t1 = __shfl_sync(0xffffffffu, v1, srcA);
        float t2 = __shfl_sync(0xffffffffu, v2, srcA);
        float t3 = __shfl_sync(0xffffffffu, v3, srcA);
        float u0 = __shfl_sync(0xffffffffu, v0, srcB);
        float u1 = __shfl_sync(0xffffffffu, v1, srcB);
        float u2 = __shfl_sync(0xffffffffu, v2, srcB);
        float u3 = __shfl_sync(0xffffffffu, v3, srcB);
        uint4 pv;
        pv.x = __float_as_uint(sel ? t1 : t0);
        pv.y = __float_as_uint(sel ? t3 : t2);
        pv.z = __float_as_uint(sel ? u1 : u0);
        pv.w = __float_as_uint(sel ? u3 : u2);
        int ct = (hc + nf * 8) >> 4;
        *(uint4*)&op[((size_t)qb * (DIM / 16) + ct) * 2048
                     + (((nf & 1) * 8 + wid) * 128) + lane * 4] = pv;
    }
}

#define ATTN_SMEM ((24576 + 128) * 4)
#define GSM128 ((3 * 4096 + 3 * 128 * 32) * 4)
#define GSM64  ((3 * 4096 + 3 * 64 * 32) * 4)

// ---------------- launch ----------------
extern "C" void kernel_launch(void* const* d_in, const int* in_sizes, int n_in,
                              void* d_out, int out_size) {
    const float* hs    = (const float*)d_in[0];
    const int*   amask = (const int*)d_in[1];
    const float* ln1w  = (const float*)d_in[2];
    const float* ln1b  = (const float*)d_in[3];
    const float* wq    = (const float*)d_in[4];
    const float* bq    = (const float*)d_in[5];
    const float* wk    = (const float*)d_in[6];
    const float* bk    = (const float*)d_in[7];
    const float* wv    = (const float*)d_in[8];
    const float* bv    = (const float*)d_in[9];
    const float* wo    = (const float*)d_in[10];
    const float* bo    = (const float*)d_in[11];
    const float* ln2w  = (const float*)d_in[12];
    const float* ln2b  = (const float*)d_in[13];
    const float* wup   = (const float*)d_in[14];
    const float* bup   = (const float*)d_in[15];
    const float* wdn   = (const float*)d_in[16];
    const float* bdn   = (const float*)d_in[17];

    float* hidden;
    unsigned *xp, *qp, *kpk, *vpk, *aop, *yp, *ffp;
    unsigned *wqp, *wkp, *wvp, *wop, *wupp, *wdp;
    cudaGetSymbolAddress((void**)&xp, g_xp);
    cudaGetSymbolAddress((void**)&qp, g_qp);
    cudaGetSymbolAddress((void**)&kpk, g_kpk);
    cudaGetSymbolAddress((void**)&vpk, g_vpk);
    cudaGetSymbolAddress((void**)&aop, g_aop);
    cudaGetSymbolAddress((void**)&hidden, g_hidden);
    cudaGetSymbolAddress((void**)&yp, g_yp);
    cudaGetSymbolAddress((void**)&ffp, g_ffp);
    cudaGetSymbolAddress((void**)&wqp, g_wqp);
    cudaGetSymbolAddress((void**)&wkp, g_wkp);
    cudaGetSymbolAddress((void**)&wvp, g_wvp);
    cudaGetSymbolAddress((void**)&wop, g_wop);
    cudaGetSymbolAddress((void**)&wupp, g_wup);
    cudaGetSymbolAddress((void**)&wdp, g_wdp);

    static int attr_set = 0;
    if (!attr_set) {
        cudaFuncSetAttribute(attn_tc, cudaFuncAttributeMaxDynamicSharedMemorySize, ATTN_SMEM);
        cudaFuncSetAttribute(gemm_qkv, cudaFuncAttributeMaxDynamicSharedMemorySize, GSM128);
        cudaFuncSetAttribute(gemm_tc<1, 128, 1>, cudaFuncAttributeMaxDynamicSharedMemorySize, GSM128);
        cudaFuncSetAttribute(gemm_tc<2, 64, 0>, cudaFuncAttributeMaxDynamicSharedMemorySize, GSM64);
        attr_set = 1;
    }

    pack_b<<<dim3(DIM / 64, DIM / 16), 256>>>(wq, wqp, DIM, DIM);
    pack_b<<<dim3(DIM / 64, DIM / 16), 256>>>(wk, wkp, DIM, DIM);
    pack_b<<<dim3(DIM / 64, DIM / 16), 256>>>(wv, wvp, DIM, DIM);
    pack_b<<<dim3(DIM / 64, DIM / 16), 256>>>(wo, wop, DIM, DIM);
    pack_b<<<dim3(FFD / 64, DIM / 16), 256>>>(wup, wupp, FFD, DIM);
    pack_b<<<dim3(DIM / 64, FFD / 16), 256>>>(wdn, wdp, DIM, FFD);

    ln_pack<<<SEQ, 256>>>(hs, ln1w, ln1b, xp);
    gemm_qkv<<<dim3(DIM / 128, SEQ / 128, 3), 256, GSM128>>>(xp, wqp, wkp, wvp,
                                                             bq, bk, bv, qp, kpk, vpk);
    attn_tc<<<dim3(SEQ / 128, NH), 256, ATTN_SMEM>>>(qp, kpk, vpk, amask, aop);
    gemm_tc<2, 64, 0><<<dim3(DIM / 64, SEQ / 128), 256, GSM64>>>(aop, wop, bo, hs,
                                                                 hidden, nullptr, DIM, DIM, 1.f);
    ln_pack<<<SEQ, 256>>>(hidden, ln2w, ln2b, yp);
    gemm_tc<1, 128, 1><<<dim3(FFD / 128, SEQ / 128), 256, GSM128>>>(yp, wupp, bup, nullptr,
                                                                    nullptr, ffp, FFD, DIM, 1.f);
    gemm_tc<2, 64, 0><<<dim3(DIM / 64, SEQ / 128), 256, GSM64>>>(ffp, wdp, bdn, hidden,
                                                                 (float*)d_out, nullptr, DIM, FFD, 1.f);
}

// round 8
// speedup vs baseline: 4.7513x; 1.0253x over previous
#include <cuda_runtime.h>
#include <math.h>

#define SEQ 4096
#define DIM 768
#define NH  12
#define HDD 64
#define FFD 3072

// ---------------- scratch (device globals) ----------------
__device__ unsigned g_xp[SEQ * DIM];    // ln1 out, packed A-frags
__device__ unsigned g_qp[SEQ * DIM];    // Q (scaled), packed A-frags
__device__ unsigned g_kpk[SEQ * DIM];   // K, attention B-frag tiles
__device__ unsigned g_vpk[SEQ * DIM];   // V, attention B-frag tiles
__device__ unsigned g_aop[SEQ * DIM];   // attention out, packed A-frags
__device__ float    g_hidden[SEQ * DIM];
__device__ unsigned g_yp[SEQ * DIM];    // ln2 out, packed A-frags
__device__ unsigned g_ffp[SEQ * FFD];   // gelu(up), packed A-frags
__device__ unsigned g_wqp[DIM * DIM];
__device__ unsigned g_wkp[DIM * DIM];
__device__ unsigned g_wvp[DIM * DIM];
__device__ unsigned g_wop[DIM * DIM];
__device__ unsigned g_wup[DIM * FFD];
__device__ unsigned g_wdp[FFD * DIM];

// ---------------- helpers ----------------
__device__ __forceinline__ void mma_tf32(float* c, const unsigned* a, const unsigned* b) {
    asm volatile(
        "mma.sync.aligned.m16n8k8.row.col.f32.tf32.tf32.f32 "
        "{%0,%1,%2,%3}, {%4,%5,%6,%7}, {%8,%9}, {%0,%1,%2,%3};"
        : "+f"(c[0]), "+f"(c[1]), "+f"(c[2]), "+f"(c[3])
        : "r"(a[0]), "r"(a[1]), "r"(a[2]), "r"(a[3]), "r"(b[0]), "r"(b[1]));
}

__device__ __forceinline__ void cpa16(void* smem, const void* gmem) {
    unsigned saddr = (unsigned)__cvta_generic_to_shared(smem);
    asm volatile("cp.async.cg.shared.global [%0], [%1], 16;" :: "r"(saddr), "l"(gmem));
}
__device__ __forceinline__ void cpa_commit() { asm volatile("cp.async.commit_group;"); }
__device__ __forceinline__ void cpa_wait0() { asm volatile("cp.async.wait_group 0;"); }
template <int W>
__device__ __forceinline__ void cpa_wait() { asm volatile("cp.async.wait_group %0;" :: "n"(W)); }

__device__ __forceinline__ float block_sum_256(float v, float* red) {
    int lane = threadIdx.x & 31;
    int wid  = threadIdx.x >> 5;
    #pragma unroll
    for (int o = 16; o; o >>= 1) v += __shfl_xor_sync(0xffffffffu, v, o);
    if (lane == 0) red[wid] = v;
    __syncthreads();
    float r;
    if (wid == 0) {
        r = (lane < 8) ? red[lane] : 0.f;
        #pragma unroll
        for (int o = 4; o; o >>= 1) r += __shfl_xor_sync(0xffffffffu, r, o);
        if (lane == 0) red[0] = r;
    }
    __syncthreads();
    r = red[0];
    __syncthreads();
    return r;
}

// ---------------- LayerNorm fused with A-frag packing ----------------
__global__ void __launch_bounds__(256) ln_pack(const float* __restrict__ in,
                                               const float* __restrict__ w,
                                               const float* __restrict__ b,
                                               unsigned* __restrict__ P) {
    __shared__ float red[32];
    int row = blockIdx.x;
    const float* x = in + (size_t)row * DIM;
    int t = threadIdx.x;
    float v0 = x[t], v1 = x[t + 256], v2 = x[t + 512];
    float mu = block_sum_256(v0 + v1 + v2, red) * (1.f / DIM);
    float d0 = v0 - mu, d1 = v1 - mu, d2 = v2 - mu;
    float var = block_sum_256(d0 * d0 + d1 * d1 + d2 * d2, red) * (1.f / DIM);
    float rstd = rsqrtf(var + 1e-5f);
    int mb = row >> 7, rl = row & 127;
    int rbase = (rl >> 4) * 128 + (rl & 7) * 16 + ((rl >> 3) & 1);
    #pragma unroll
    for (int p = 0; p < 3; p++) {
        int col = t + p * 256;
        float d = (p == 0) ? d0 : (p == 1) ? d1 : d2;
        float val = d * rstd * w[col] + b[col];
        int kt = col >> 4, cc = col & 15, c4 = cc >> 2, j = cc & 3;
        P[((size_t)mb * 48 + kt) * 2048 + (c4 >> 1) * 1024 + rbase
          + 2 * (c4 & 1) + 4 * j] = __float_as_uint(val);
    }
}

// ---------------- batched weight packs ----------------
__device__ __forceinline__ void pack_b_block(const float* __restrict__ B,
                                             unsigned* __restrict__ P,
                                             int nb, int kt, int N, int K16) {
    unsigned* dst = P + ((size_t)nb * K16 + kt) * 1024;
    int tid = threadIdx.x;
    int kr = tid >> 4, c4 = tid & 15;
    float4 v = *(const float4*)(B + (size_t)(kt * 16 + kr) * N + nb * 64 + c4 * 4);
    int base = ((kr >> 3) * 8 + (c4 >> 1)) * 64 + (c4 & 1) * 32
               + (kr & 3) * 2 + ((kr >> 2) & 1);
    dst[base]      = __float_as_uint(v.x);
    dst[base + 8]  = __float_as_uint(v.y);
    dst[base + 16] = __float_as_uint(v.z);
    dst[base + 24] = __float_as_uint(v.w);
}

// 4x 768x768 weights: grid (576, 4)
__global__ void __launch_bounds__(256) pack_b4(const float* __restrict__ w0,
                                               const float* __restrict__ w1,
                                               const float* __restrict__ w2,
                                               const float* __restrict__ w3,
                                               unsigned* __restrict__ p0,
                                               unsigned* __restrict__ p1,
                                               unsigned* __restrict__ p2,
                                               unsigned* __restrict__ p3) {
    int z = blockIdx.y;
    const float* B = (z == 0) ? w0 : (z == 1) ? w1 : (z == 2) ? w2 : w3;
    unsigned* P = (z == 0) ? p0 : (z == 1) ? p1 : (z == 2) ? p2 : p3;
    int nb = blockIdx.x / 48, kt = blockIdx.x % 48;
    pack_b_block(B, P, nb, kt, DIM, 48);
}

// up (768x3072) and down (3072x768): grid (2304, 2)
__global__ void __launch_bounds__(256) pack_b2(const float* __restrict__ wu,
                                               const float* __restrict__ wd,
                                               unsigned* __restrict__ pu,
                                               unsigned* __restrict__ pd) {
    int z = blockIdx.y;
    const float* B = z ? wd : wu;
    unsigned* P = z ? pd : pu;
    int N = z ? DIM : FFD;
    int K16 = z ? (FFD / 16) : (DIM / 16);
    int nb = blockIdx.x / K16, kt = blockIdx.x % K16;
    pack_b_block(B, P, nb, kt, N, K16);
}

// ---------------- TF32 GEMM, packed operands, 32-K stages, 1 sync/stage ----------
// OUTP: 0 row-major C, 1 packed A-frag Cp, 2 attention-K B-frag Cp, 3 attention-V B-frag Cp
template <int EPI, int BN, int OUTP>
__device__ __forceinline__ void gemm_core(const unsigned* __restrict__ Ap,
                                          const unsigned* __restrict__ Bp,
                                          const float* __restrict__ bias,
                                          const float* __restrict__ res,
                                          float* __restrict__ C,
                                          unsigned* __restrict__ Cp,
                                          int N, int K, float scale) {
    constexpr int NB = BN / 64;
    constexpr int MI = (BN == 128) ? 4 : 2;
    constexpr int ST = (BN == 64) ? 4 : 3;
    constexpr int BN32 = BN * 32;
    extern __shared__ unsigned smem_u[];
    unsigned* sA = smem_u;                 // ST * 4096
    unsigned* sB = smem_u + ST * 4096;     // ST * BN32

    int tid = threadIdx.x, lane = tid & 31, wid = tid >> 5;
    int wm = (BN == 128) ? (wid & 1) : (wid & 3);
    int wn = (BN == 128) ? (wid >> 1) : (wid >> 2);
    int bx = blockIdx.x, by = blockIdx.y;
    int K16 = K >> 4, nt32 = K >> 5;

    const uint4* Ab = (const uint4*)(Ap + (size_t)by * K16 * 2048);
    float acc[MI][4][4] = {};

    auto issue = [&](int kt32, int st) {
        const uint4* ga = Ab + (size_t)kt32 * 1024;
        uint4* da = (uint4*)&sA[st * 4096];
        #pragma unroll
        for (int i = 0; i < 4; i++) cpa16(&da[tid + i * 256], &ga[tid + i * 256]);
        #pragma unroll
        for (int nb = 0; nb < NB; nb++) {
            const uint4* gb = (const uint4*)(Bp + ((size_t)(bx * NB + nb) * K16 + kt32 * 2) * 1024);
            uint4* db = (uint4*)&sB[st * BN32 + nb * 2048];
            cpa16(&db[tid], &gb[tid]);
            cpa16(&db[tid + 256], &gb[tid + 256]);
        }
    };

    #pragma unroll
    for (int p = 0; p < ST - 1; p++) { issue(p, p); cpa_commit(); }

    for (int kt = 0; kt < nt32; kt++) {
        int st = kt % ST;
        cpa_wait<ST - 2>();
        __syncthreads();
        if (kt + ST - 1 < nt32) issue(kt + ST - 1, (kt + ST - 1) % ST);
        cpa_commit();
        #pragma unroll
        for (int half = 0; half < 2; half++) {
            #pragma unroll
            for (int ks = 0; ks < 2; ks++) {
                uint4 af[MI];
                uint2 bf[4];
                #pragma unroll
                for (int mi = 0; mi < MI; mi++)
                    af[mi] = *(const uint4*)&sA[st * 4096 + half * 2048
                                                + (ks * 8 + wm * MI + mi) * 128 + lane * 4];
                #pragma unroll
                for (int ni = 0; ni < 4; ni++) {
                    int nf = wn * 4 + ni;
                    int idx = st * BN32 + ((BN == 128) ? (nf >> 3) * 2048 : 0) + half * 1024
                              + (ks * 8 + ((BN == 128) ? (nf & 7) : nf)) * 64 + lane * 2;
                    bf[ni] = *(const uint2*)&sB[idx];
                }
                #pragma unroll
                for (int mi = 0; mi < MI; mi++)
                    #pragma unroll
                    for (int ni = 0; ni < 4; ni++)
                        mma_tf32(acc[mi][ni], &af[mi].x, &bf[ni].x);
            }
        }
    }
    __syncthreads();

    int srcA = (lane & ~3) | ((lane & 3) >> 1);
    int srcB = srcA | 2;
    bool sel = lane & 1;
    int srcV0 = (lane & 3) * 4 + (lane >> 3);
    int srcV1 = srcV0 + 16;
    bool selV = (lane >> 2) & 1;

    #pragma unroll
    for (int ni = 0; ni < 4; ni++) {
        int colb = bx * BN + wn * 32 + ni * 8;
        int col = colb + (lane & 3) * 2;
        float b0 = bias[col], b1 = bias[col + 1];
        #pragma unroll
        for (int mi = 0; mi < MI; mi++) {
            int r0b = by * 128 + wm * (16 * MI) + mi * 16;
            int r0 = r0b + (lane >> 2);
            float v0 = acc[mi][ni][0] + b0;
            float v1 = acc[mi][ni][1] + b1;
            float v2 = acc[mi][ni][2] + b0;
            float v3 = acc[mi][ni][3] + b1;
            if (EPI == 1) {
                v0 = 0.5f * v0 * (1.f + erff(v0 * 0.70710678118654752f));
                v1 = 0.5f * v1 * (1.f + erff(v1 * 0.70710678118654752f));
                v2 = 0.5f * v2 * (1.f + erff(v2 * 0.70710678118654752f));
                v3 = 0.5f * v3 * (1.f + erff(v3 * 0.70710678118654752f));
            }
            if (EPI == 2) {
                float2 r0v = *(const float2*)&res[(size_t)r0 * N + col];
                float2 r1v = *(const float2*)&res[(size_t)(r0 + 8) * N + col];
                v0 += r0v.x; v1 += r0v.y; v2 += r1v.x; v3 += r1v.y;
            }
            if (OUTP == 0) {
                float2 o0; o0.x = v0; o0.y = v1;
                float2 o1; o1.x = v2; o1.y = v3;
                *(float2*)&C[(size_t)r0 * N + col] = o0;
                *(float2*)&C[(size_t)(r0 + 8) * N + col] = o1;
            } else if (OUTP == 1) {
                v0 *= scale; v1 *= scale; v2 *= scale; v3 *= scale;
                float t0 = __shfl_sync(0xffffffffu, v0, srcA);
                float t1 = __shfl_sync(0xffffffffu, v1, srcA);
                float t2 = __shfl_sync(0xffffffffu, v2, srcA);
                float t3 = __shfl_sync(0xffffffffu, v3, srcA);
                float u0 = __shfl_sync(0xffffffffu, v0, srcB);
                float u1 = __shfl_sync(0xffffffffu, v1, srcB);
                float u2 = __shfl_sync(0xffffffffu, v2, srcB);
                float u3 = __shfl_sync(0xffffffffu, v3, srcB);
                uint4 pv;
                pv.x = __float_as_uint(sel ? t1 : t0);
                pv.y = __float_as_uint(sel ? t3 : t2);
                pv.z = __float_as_uint(sel ? u1 : u0);
                pv.w = __float_as_uint(sel ? u3 : u2);
                int ct = colb >> 4;
                *(uint4*)&Cp[((size_t)by * (N >> 4) + ct) * 2048
                             + (((ni & 1) * 8 + wm * MI + mi) * 128) + lane * 4] = pv;
            } else if (OUTP == 2) {
                float t0 = __shfl_sync(0xffffffffu, v0, srcA);
                float t1 = __shfl_sync(0xffffffffu, v1, srcA);
                float t2 = __shfl_sync(0xffffffffu, v2, srcA);
                float t3 = __shfl_sync(0xffffffffu, v3, srcA);
                float u0 = __shfl_sync(0xffffffffu, v0, srcB);
                float u1 = __shfl_sync(0xffffffffu, v1, srcB);
                float u2 = __shfl_sync(0xffffffffu, v2, srcB);
                float u3 = __shfl_sync(0xffffffffu, v3, srcB);
                int head = colb >> 6, ksd = (colb & 63) >> 3;
                int kb = r0b >> 6, nf = (r0b >> 3) & 7;
                size_t tb = ((size_t)head * (SEQ / 64) + kb) * 4096;
                uint2 lo, hi;
                lo.x = __float_as_uint(sel ? t1 : t0);
                lo.y = __float_as_uint(sel ? u1 : u0);
                hi.x = __float_as_uint(sel ? t3 : t2);
                hi.y = __float_as_uint(sel ? u3 : u2);
                *(uint2*)&Cp[tb + (ksd * 8 + nf) * 64 + lane * 2] = lo;
                *(uint2*)&Cp[tb + (ksd * 8 + nf + 1) * 64 + lane * 2] = hi;
            } else {
                float w0 = __shfl_sync(0xffffffffu, v0, srcV0);
                float w1 = __shfl_sync(0xffffffffu, v1, srcV0);
                float x0 = __shfl_sync(0xffffffffu, v0, srcV1);
                float x1 = __shfl_sync(0xffffffffu, v1, srcV1);
                float y0 = __shfl_sync(0xffffffffu, v2, srcV0);
                float y1 = __shfl_sync(0xffffffffu, v3, srcV0);
                float z0 = __shfl_sync(0xffffffffu, v2, srcV1);
                float z1 = __shfl_sync(0xffffffffu, v3, srcV1);
                int head = colb >> 6, nfd = (colb & 63) >> 3;
                int kb = r0b >> 6, ksv = (r0b >> 3) & 7;
                size_t tb = ((size_t)head * (SEQ / 64) + kb) * 4096;
                uint2 lo, hi;
                lo.x = __float_as_uint(selV ? w1 : w0);
                lo.y = __float_as_uint(selV ? x1 : x0);
                hi.x = __float_as_uint(selV ? y1 : y0);
                hi.y = __float_as_uint(selV ? z1 : z0);
                *(uint2*)&Cp[tb + (ksv * 8 + nfd) * 64 + lane * 2] = lo;
                *(uint2*)&Cp[tb + ((ksv + 1) * 8 + nfd) * 64 + lane * 2] = hi;
            }
        }
    }
}

template <int EPI, int BN, int OUTP>
__global__ void __launch_bounds__(256, 2) gemm_tc(const unsigned* __restrict__ Ap,
                                                  const unsigned* __restrict__ Bp,
                                                  const float* __restrict__ bias,
                                                  const float* __restrict__ res,
                                                  float* __restrict__ C,
                                                  unsigned* __restrict__ Cp,
                                                  int N, int K, float scale) {
    gemm_core<EPI, BN, OUTP>(Ap, Bp, bias, res, C, Cp, N, K, scale);
}

__global__ void __launch_bounds__(256, 2) gemm_qkv(const unsigned* __restrict__ Ap,
                                                   const unsigned* __restrict__ B0,
                                                   const unsigned* __restrict__ B1,
                                                   const unsigned* __restrict__ B2,
                                                   const float* __restrict__ c0,
                                                   const float* __restrict__ c1,
                                                   const float* __restrict__ c2,
                                                   unsigned* __restrict__ Qp,
                                                   unsigned* __restrict__ Kp,
                                                   unsigned* __restrict__ Vp) {
    if (blockIdx.z == 0)
        gemm_core<0, 128, 1>(Ap, B0, c0, nullptr, nullptr, Qp, DIM, DIM, 0.125f);
    else if (blockIdx.z == 1)
        gemm_core<0, 128, 2>(Ap, B1, c1, nullptr, nullptr, Kp, DIM, DIM, 1.f);
    else
        gemm_core<0, 128, 3>(Ap, B2, c2, nullptr, nullptr, Vp, DIM, DIM, 1.f);
}

// ---------------- TF32 flash attention, fully packed I/O ----------------
__global__ void __launch_bounds__(256, 2) attn_tc(const unsigned* __restrict__ qp,
                                                  const unsigned* __restrict__ kp,
                                                  const unsigned* __restrict__ vp,
                                                  const int* __restrict__ amask,
                                                  unsigned* __restrict__ op) {
    extern __shared__ unsigned smbuf[];
    unsigned* sQ = smbuf;                 // 8192
    unsigned* sK = smbuf + 8192;          // 2 x 4096
    unsigned* sV = smbuf + 16384;         // 2 x 4096
    int* sMask = (int*)(smbuf + 24576);   // 2 x 64

    int tid = threadIdx.x, lane = tid & 31, wid = tid >> 5;
    int head = blockIdx.y;
    int qb = gridDim.x - 1 - blockIdx.x;
    int hc = head * HDD;
    int qrow0 = qb * 128;

    int nkb = 2 * qb + 2;
    {
        const uint4* qg = (const uint4*)(qp + ((size_t)qb * 48 + head * 4) * 2048);
        uint4* dq = (uint4*)sQ;
        #pragma unroll
        for (int it = 0; it < 8; it++) cpa16(&dq[tid + it * 256], &qg[tid + it * 256]);
        size_t tb = ((size_t)head * (SEQ / 64)) * 4096;
        const uint4* kg = (const uint4*)(kp + tb);
        const uint4* vg = (const uint4*)(vp + tb);
        #pragma unroll
        for (int it = 0; it < 4; it++) {
            int i = tid + it * 256;
            cpa16(&((uint4*)sK)[i], &kg[i]);
            cpa16(&((uint4*)sV)[i], &vg[i]);
        }
        cpa_commit();
        if (tid < 64) sMask[tid] = amask[tid];
    }

    float m0 = -1e30f, m1 = -1e30f, l0 = 0.f, l1 = 0.f;
    float oacc[8][4] = {};
    int r0g = qrow0 + wid * 16 + (lane >> 2);

    int srcA = (lane & ~3) | ((lane & 3) >> 1);
    int srcB = srcA | 2;
    bool sel = lane & 1;

    for (int kb = 0; kb < nkb; kb++) {
        int cur = kb & 1;
        cpa_wait0();
        __syncthreads();

        if (kb + 1 < nkb) {
            size_t tb = ((size_t)head * (SEQ / 64) + (kb + 1)) * 4096;
            const uint4* kg = (const uint4*)(kp + tb);
            const uint4* vg = (const uint4*)(vp + tb);
            uint4* dk = (uint4*)(sK + (cur ^ 1) * 4096);
            uint4* dv = (uint4*)(sV + (cur ^ 1) * 4096);
            #pragma unroll
            for (int it = 0; it < 4; it++) {
                int i = tid + it * 256;
                cpa16(&dk[i], &kg[i]);
                cpa16(&dv[i], &vg[i]);
            }
            cpa_commit();
            if (tid < 64) sMask[(cur ^ 1) * 64 + tid] = amask[(kb + 1) * 64 + tid];
        }

        const unsigned* cK = sK + cur * 4096;
        const unsigned* cV = sV + cur * 4096;
        const int* cM = sMask + cur * 64;

        float s[8][4] = {};
        #pragma unroll
        for (int ks = 0; ks < 8; ks++) {
            uint4 a = *(const uint4*)&sQ[(ks >> 1) * 2048 + (ks & 1) * 1024
                                          + wid * 128 + lane * 4];
            #pragma unroll
            for (int nf = 0; nf < 8; nf++) {
                uint2 b = *(const uint2*)&cK[(ks * 8 + nf) * 64 + lane * 2];
                mma_tf32(s[nf], &a.x, &b.x);
            }
        }

        // masking: full causal check only on the two diagonal tiles
        if (kb >= 2 * qb) {
            #pragma unroll
            for (int nf = 0; nf < 8; nf++) {
                int cl = nf * 8 + (lane & 3) * 2;
                int c0 = kb * 64 + cl;
                bool p0 = (cM[cl] == 0), p1 = (cM[cl + 1] == 0);
                if ((c0 > r0g) || p0)           s[nf][0] = -1e30f;
                if ((c0 + 1 > r0g) || p1)       s[nf][1] = -1e30f;
                if ((c0 > r0g + 8) || p0)       s[nf][2] = -1e30f;
                if ((c0 + 1 > r0g + 8) || p1)   s[nf][3] = -1e30f;
            }
        } else {
            #pragma unroll
            for (int nf = 0; nf < 8; nf++) {
                int cl = nf * 8 + (lane & 3) * 2;
                float pn0 = cM[cl] ? 0.f : -1e30f;
                float pn1 = cM[cl + 1] ? 0.f : -1e30f;
                s[nf][0] += pn0; s[nf][1] += pn1;
                s[nf][2] += pn0; s[nf][3] += pn1;
            }
        }

        float mx0 = -1e30f, mx1 = -1e30f;
        #pragma unroll
        for (int nf = 0; nf < 8; nf++) {
            mx0 = fmaxf(mx0, fmaxf(s[nf][0], s[nf][1]));
            mx1 = fmaxf(mx1, fmaxf(s[nf][2], s[nf][3]));
        }
        mx0 = fmaxf(mx0, __shfl_xor_sync(0xffffffffu, mx0, 1));
        mx0 = fmaxf(mx0, __shfl_xor_sync(0xffffffffu, mx0, 2));
        mx1 = fmaxf(mx1, __shfl_xor_sync(0xffffffffu, mx1, 1));
        mx1 = fmaxf(mx1, __shfl_xor_sync(0xffffffffu, mx1, 2));
        float mn0 = fmaxf(m0, mx0), mn1 = fmaxf(m1, mx1);
        float f0 = __expf(m0 - mn0), f1 = __expf(m1 - mn1);
        float sum0 = 0.f, sum1 = 0.f;
        #pragma unroll
        for (int nf = 0; nf < 8; nf++) {
            s[nf][0] = __expf(s[nf][0] - mn0);
            s[nf][1] = __expf(s[nf][1] - mn0);
            s[nf][2] = __expf(s[nf][2] - mn1);
            s[nf][3] = __expf(s[nf][3] - mn1);
            sum0 += s[nf][0] + s[nf][1];
            sum1 += s[nf][2] + s[nf][3];
        }
        sum0 += __shfl_xor_sync(0xffffffffu, sum0, 1);
        sum0 += __shfl_xor_sync(0xffffffffu, sum0, 2);
        sum1 += __shfl_xor_sync(0xffffffffu, sum1, 1);
        sum1 += __shfl_xor_sync(0xffffffffu, sum1, 2);
        l0 = l0 * f0 + sum0;
        l1 = l1 * f1 + sum1;
        m0 = mn0; m1 = mn1;
        #pragma unroll
        for (int nf = 0; nf < 8; nf++) {
            oacc[nf][0] *= f0; oacc[nf][1] *= f0;
            oacc[nf][2] *= f1; oacc[nf][3] *= f1;
        }

        #pragma unroll
        for (int ks = 0; ks < 8; ks++) {
            float t0 = __shfl_sync(0xffffffffu, s[ks][0], srcA);
            float t1 = __shfl_sync(0xffffffffu, s[ks][1], srcA);
            float t2 = __shfl_sync(0xffffffffu, s[ks][2], srcA);
            float t3 = __shfl_sync(0xffffffffu, s[ks][3], srcA);
            float u0 = __shfl_sync(0xffffffffu, s[ks][0], srcB);
            float u1 = __shfl_sync(0xffffffffu, s[ks][1], srcB);
            float u2 = __shfl_sync(0xffffffffu, s[ks][2], srcB);
            float u3 = __shfl_sync(0xffffffffu, s[ks][3], srcB);
            unsigned a[4];
            a[0] = __float_as_uint(sel ? t1 : t0);
            a[1] = __float_as_uint(sel ? t3 : t2);
            a[2] = __float_as_uint(sel ? u1 : u0);
            a[3] = __float_as_uint(sel ? u3 : u2);
            #pragma unroll
            for (int nf = 0; nf < 8; nf++) {
                uint2 b = *(const uint2*)&cV[(ks * 8 + nf) * 64 + lane * 2];
                mma_tf32(oacc[nf], a, &b.x);
            }
        }
    }

    float inv0 = 1.f / l0, inv1 = 1.f / l1;
    #pragma unroll
    for (int nf = 0; nf < 8; nf++) {
        float v0 = oacc[nf][0] * inv0;
        float v1 = oacc[nf][1] * inv0;
        float v2 = oacc[nf][2] * inv1;
        float v3 = oacc[nf][3] * inv1;
        float t0 = __shfl_sync(0xffffffffu, v0, srcA);
        float t1 = __shfl_sync(0xffffffffu, v1, srcA);
        float t2 = __shfl_sync(0xffffffffu, v2, srcA);
        float t3 = __shfl_sync(0xffffffffu, v3, srcA);
        float u0 = __shfl_sync(0xffffffffu, v0, srcB);
        float u1 = __shfl_sync(0xffffffffu, v1, srcB);
        float u2 = __shfl_sync(0xffffffffu, v2, srcB);
        float u3 = __shfl_sync(0xffffffffu, v3, srcB);
        uint4 pv;
        pv.x = __float_as_uint(sel ? t1 : t0);
        pv.y = __float_as_uint(sel ? t3 : t2);
        pv.z = __float_as_uint(sel ? u1 : u0);
        pv.w = __float_as_uint(sel ? u3 : u2);
        int ct = (hc + nf * 8) >> 4;
        *(uint4*)&op[((size_t)qb * (DIM / 16) + ct) * 2048
                     + (((nf & 1) * 8 + wid) * 128) + lane * 4] = pv;
    }
}

#define ATTN_SMEM ((24576 + 128) * 4)
#define GSM128 ((3 * 4096 + 3 * 128 * 32) * 4)
#define GSM64  ((4 * 4096 + 4 * 64 * 32) * 4)

// ---------------- launch ----------------
extern "C" void kernel_launch(void* const* d_in, const int* in_sizes, int n_in,
                              void* d_out, int out_size) {
    const float* hs    = (const float*)d_in[0];
    const int*   amask = (const int*)d_in[1];
    const float* ln1w  = (const float*)d_in[2];
    const float* ln1b  = (const float*)d_in[3];
    const float* wq    = (const float*)d_in[4];
    const float* bq    = (const float*)d_in[5];
    const float* wk    = (const float*)d_in[6];
    const float* bk    = (const float*)d_in[7];
    const float* wv    = (const float*)d_in[8];
    const float* bv    = (const float*)d_in[9];
    const float* wo    = (const float*)d_in[10];
    const float* bo    = (const float*)d_in[11];
    const float* ln2w  = (const float*)d_in[12];
    const float* ln2b  = (const float*)d_in[13];
    const float* wup   = (const float*)d_in[14];
    const float* bup   = (const float*)d_in[15];
    const float* wdn   = (const float*)d_in[16];
    const float* bdn   = (const float*)d_in[17];

    float* hidden;
    unsigned *xp, *qp, *kpk, *vpk, *aop, *yp, *ffp;
    unsigned *wqp, *wkp, *wvp, *wop, *wupp, *wdp;
    cudaGetSymbolAddress((void**)&xp, g_xp);
    cudaGetSymbolAddress((void**)&qp, g_qp);
    cudaGetSymbolAddress((void**)&kpk, g_kpk);
    cudaGetSymbolAddress((void**)&vpk, g_vpk);
    cudaGetSymbolAddress((void**)&aop, g_aop);
    cudaGetSymbolAddress((void**)&hidden, g_hidden);
    cudaGetSymbolAddress((void**)&yp, g_yp);
    cudaGetSymbolAddress((void**)&ffp, g_ffp);
    cudaGetSymbolAddress((void**)&wqp, g_wqp);
    cudaGetSymbolAddress((void**)&wkp, g_wkp);
    cudaGetSymbolAddress((void**)&wvp, g_wvp);
    cudaGetSymbolAddress((void**)&wop, g_wop);
    cudaGetSymbolAddress((void**)&wupp, g_wup);
    cudaGetSymbolAddress((void**)&wdp, g_wdp);

    static int attr_set = 0;
    if (!attr_set) {
        cudaFuncSetAttribute(attn_tc, cudaFuncAttributeMaxDynamicSharedMemorySize, ATTN_SMEM);
        cudaFuncSetAttribute(gemm_qkv, cudaFuncAttributeMaxDynamicSharedMemorySize, GSM128);
        cudaFuncSetAttribute(gemm_tc<1, 128, 1>, cudaFuncAttributeMaxDynamicSharedMemorySize, GSM128);
        cudaFuncSetAttribute(gemm_tc<2, 64, 0>, cudaFuncAttributeMaxDynamicSharedMemorySize, GSM64);
        attr_set = 1;
    }

    pack_b4<<<dim3(576, 4), 256>>>(wq, wk, wv, wo, wqp, wkp, wvp, wop);
    pack_b2<<<dim3(2304, 2), 256>>>(wup, wdn, wupp, wdp);

    ln_pack<<<SEQ, 256>>>(hs, ln1w, ln1b, xp);
    gemm_qkv<<<dim3(DIM / 128, SEQ / 128, 3), 256, GSM128>>>(xp, wqp, wkp, wvp,
                                                             bq, bk, bv, qp, kpk, vpk);
    attn_tc<<<dim3(SEQ / 128, NH), 256, ATTN_SMEM>>>(qp, kpk, vpk, amask, aop);
    gemm_tc<2, 64, 0><<<dim3(DIM / 64, SEQ / 128), 256, GSM64>>>(aop, wop, bo, hs,
                                                                 hidden, nullptr, DIM, DIM, 1.f);
    ln_pack<<<SEQ, 256>>>(hidden, ln2w, ln2b, yp);
    gemm_tc<1, 128, 1><<<dim3(FFD / 128, SEQ / 128), 256, GSM128>>>(yp, wupp, bup, nullptr,
                                                                    nullptr, ffp, FFD, DIM, 1.f);
    gemm_tc<2, 64, 0><<<dim3(DIM / 64, SEQ / 128), 256, GSM64>>>(ffp, wdp, bdn, hidden,
                                                                 (float*)d_out, nullptr, DIM, FFD, 1.f);
}